// round 8
// baseline (speedup 1.0000x reference)
#include <cuda_runtime.h>
#include <cuda_bf16.h>
#include <math.h>
#include <cstdint>

#define Bq   8
#define Tq   2048
#define Dq   1024
#define HSq  128
#define BT   (Bq * Tq)        // 16384 rows
#define NTOT 384              // 3 * HS

// Scratch (device globals — no allocs allowed). bf16 hi/lo split storage.
__device__ __align__(256) __nv_bfloat16 g_x_hi[BT * Dq];
__device__ __align__(256) __nv_bfloat16 g_x_lo[BT * Dq];
__device__ __align__(256) __nv_bfloat16 g_wt_hi[NTOT * Dq];   // W^T, K-major (Wq pre-scaled)
__device__ __align__(256) __nv_bfloat16 g_wt_lo[NTOT * Dq];
__device__ __align__(256) __nv_bfloat16 g_q_hi[BT * HSq];
__device__ __align__(256) __nv_bfloat16 g_q_lo[BT * HSq];
__device__ __align__(256) __nv_bfloat16 g_k_hi[BT * HSq];
__device__ __align__(256) __nv_bfloat16 g_k_lo[BT * HSq];
__device__ __align__(256) __nv_bfloat16 g_v_hi[BT * HSq];
__device__ __align__(256) __nv_bfloat16 g_v_lo[BT * HSq];

// ---------------------------------------------------------------------------
// Helpers
// ---------------------------------------------------------------------------
__device__ __forceinline__ void mma_bf16(float* c, const uint32_t* a, const uint32_t* b) {
    asm volatile(
        "mma.sync.aligned.m16n8k16.row.col.f32.bf16.bf16.f32 "
        "{%0,%1,%2,%3}, {%4,%5,%6,%7}, {%8,%9}, {%0,%1,%2,%3};"
        : "+f"(c[0]), "+f"(c[1]), "+f"(c[2]), "+f"(c[3])
        : "r"(a[0]), "r"(a[1]), "r"(a[2]), "r"(a[3]), "r"(b[0]), "r"(b[1]));
}
__device__ __forceinline__ void ldsm_x4(uint32_t* r, uint32_t addr) {
    asm volatile("ldmatrix.sync.aligned.m8n8.x4.shared.b16 {%0,%1,%2,%3}, [%4];"
                 : "=r"(r[0]), "=r"(r[1]), "=r"(r[2]), "=r"(r[3]) : "r"(addr));
}
__device__ __forceinline__ void ldsm_x4_t(uint32_t* r, uint32_t addr) {
    asm volatile("ldmatrix.sync.aligned.m8n8.x4.trans.shared.b16 {%0,%1,%2,%3}, [%4];"
                 : "=r"(r[0]), "=r"(r[1]), "=r"(r[2]), "=r"(r[3]) : "r"(addr));
}
__device__ __forceinline__ uint32_t smem_u32(const void* p) {
    uint32_t a;
    asm("{ .reg .u64 t; cvta.to.shared.u64 t, %1; cvt.u32.u64 %0, t; }"
        : "=r"(a) : "l"(p));
    return a;
}
__device__ __forceinline__ void cp16(uint32_t dst, const void* src) {
    asm volatile("cp.async.cg.shared.global [%0], [%1], 16;" :: "r"(dst), "l"(src));
}
#define CP_COMMIT() asm volatile("cp.async.commit_group;" ::: "memory")
#define CP_WAIT0()  asm volatile("cp.async.wait_group 0;" ::: "memory")
#define CP_WAIT1()  asm volatile("cp.async.wait_group 1;" ::: "memory")

// split pair of floats into packed bf16 hi/lo
__device__ __forceinline__ void split2(float v0, float v1, uint32_t& hi, uint32_t& lo) {
    __nv_bfloat16 h0 = __float2bfloat16_rn(v0);
    __nv_bfloat16 h1 = __float2bfloat16_rn(v1);
    float l0 = v0 - __bfloat162float(h0);
    float l1 = v1 - __bfloat162float(h1);
    hi = (uint32_t)__bfloat16_as_ushort(h0) | ((uint32_t)__bfloat16_as_ushort(h1) << 16);
    __nv_bfloat16 g0 = __float2bfloat16_rn(l0);
    __nv_bfloat16 g1 = __float2bfloat16_rn(l1);
    lo = (uint32_t)__bfloat16_as_ushort(g0) | ((uint32_t)__bfloat16_as_ushort(g1) << 16);
}

// ---------------------------------------------------------------------------
// Kernel 0a: split x -> bf16 hi/lo. 8 floats per thread.
// ---------------------------------------------------------------------------
__global__ __launch_bounds__(256) void prep_x_kernel(const float* __restrict__ x)
{
    size_t i = ((size_t)blockIdx.x * 256 + threadIdx.x) * 8;
    float4 a = *(const float4*)&x[i];
    float4 b = *(const float4*)&x[i + 4];
    uint32_t h0, l0, h1, l1, h2, l2, h3, l3;
    split2(a.x, a.y, h0, l0); split2(a.z, a.w, h1, l1);
    split2(b.x, b.y, h2, l2); split2(b.z, b.w, h3, l3);
    *(uint4*)&g_x_hi[i] = make_uint4(h0, h1, h2, h3);
    *(uint4*)&g_x_lo[i] = make_uint4(l0, l1, l2, l3);
}

// ---------------------------------------------------------------------------
// Kernel 0b: transpose + split-convert weights (Wq scaled by 128^-0.5).
// ---------------------------------------------------------------------------
__global__ void prep_w_kernel(const float* __restrict__ Wq,
                              const float* __restrict__ Wk,
                              const float* __restrict__ Wv)
{
    __shared__ float t[32][33];
    const int k0 = blockIdx.x * 32;
    const int n0 = blockIdx.y * 32;
    const int slab = n0 >> 7;
    const float* W = (slab == 0) ? Wq : (slab == 1) ? Wk : Wv;
    const float sc = (slab == 0) ? 0.08838834764831845f : 1.0f;
    const int nn0 = n0 & 127;
    const int tx = threadIdx.x, ty = threadIdx.y;

    #pragma unroll
    for (int i = 0; i < 4; i++)
        t[ty * 4 + i][tx] = W[(size_t)(k0 + ty * 4 + i) * HSq + nn0 + tx] * sc;
    __syncthreads();
    #pragma unroll
    for (int i = 0; i < 4; i++) {
        int nr = ty * 4 + i;
        float v = t[tx][nr];
        __nv_bfloat16 hi = __float2bfloat16_rn(v);
        __nv_bfloat16 lo = __float2bfloat16_rn(v - __bfloat162float(hi));
        size_t o = (size_t)(n0 + nr) * Dq + k0 + tx;
        g_wt_hi[o] = hi;
        g_wt_lo[o] = lo;
    }
}

// ---------------------------------------------------------------------------
// Kernel 1: QKV projection, HMMA + cp.async double buffer + ldmatrix frags.
// Grid (128 M-tiles, 3 slabs), block 256 (8 warps, 4x2). BM=128 BN=128 BK=32.
// ---------------------------------------------------------------------------
#define PS      80            // smem row pitch bytes (40 bf16)
#define P_ARR   (128 * PS)    // 10240
#define P_XH    0
#define P_XL    (1 * P_ARR)
#define P_WH    (2 * P_ARR)
#define P_WL    (3 * P_ARR)
#define P_BUF   (4 * P_ARR)   // 40960
#define PROJ_SMEM (2 * P_BUF) // 81920

__global__ __launch_bounds__(256, 2) void proj_mma_kernel()
{
    extern __shared__ __align__(16) char smc[];
    const uint32_t sb = smem_u32(smc);
    const int tid = threadIdx.x;
    const int w   = tid >> 5;
    const int L   = tid & 31;
    const int m0  = blockIdx.x * 128;
    const int nt  = blockIdx.y;                   // 0:q 1:k 2:v
    __nv_bfloat16* out_hi = (nt == 0) ? g_q_hi : (nt == 1) ? g_k_hi : g_v_hi;
    __nv_bfloat16* out_lo = (nt == 0) ? g_q_lo : (nt == 1) ? g_k_lo : g_v_lo;

    const __nv_bfloat16* whi = g_wt_hi + (size_t)nt * HSq * Dq;
    const __nv_bfloat16* wlo = g_wt_lo + (size_t)nt * HSq * Dq;
    const __nv_bfloat16* xhi = g_x_hi + (size_t)m0 * Dq;
    const __nv_bfloat16* xlo = g_x_lo + (size_t)m0 * Dq;

    const int mrow  = (w & 3) * 32;
    const int nbase = (w >> 2) * 64;

    float c[2][8][4];
    #pragma unroll
    for (int mt = 0; mt < 2; mt++)
        #pragma unroll
        for (int j = 0; j < 8; j++)
            #pragma unroll
            for (int r = 0; r < 4; r++) c[mt][j][r] = 0.f;

    auto prefetch = [&](int ch, uint32_t bb) {
        const int kb = ch * 32;
        #pragma unroll
        for (int i = 0; i < 2; i++) {
            int idx = tid + i * 256;
            int r = idx >> 2, q = idx & 3;
            uint32_t d = bb + r * PS + q * 16;
            cp16(d + P_XH, xhi + (size_t)r * Dq + kb + q * 8);
            cp16(d + P_XL, xlo + (size_t)r * Dq + kb + q * 8);
            cp16(d + P_WH, whi + (size_t)r * Dq + kb + q * 8);
            cp16(d + P_WL, wlo + (size_t)r * Dq + kb + q * 8);
        }
    };

    prefetch(0, sb);
    CP_COMMIT();

    for (int ch = 0; ch < Dq / 32; ch++) {
        if (ch + 1 < Dq / 32) prefetch(ch + 1, sb + ((ch + 1) & 1) * P_BUF);
        CP_COMMIT();
        CP_WAIT1();
        __syncthreads();

        const uint32_t base = sb + (ch & 1) * P_BUF;

        // A fragments: ldmatrix.x4, [mt][ks][4] for hi and lo
        uint32_t ah[2][2][4], al[2][2][4];
        #pragma unroll
        for (int mt = 0; mt < 2; mt++) {
            uint32_t arow = base + P_XH
                + (uint32_t)(mrow + mt * 16 + (L & 7) + ((L >> 3) & 1) * 8) * PS
                + (L >> 4) * 16;
            #pragma unroll
            for (int ks = 0; ks < 2; ks++) {
                ldsm_x4(ah[mt][ks], arow + ks * 32);
                ldsm_x4(al[mt][ks], arow + ks * 32 + (P_XL - P_XH));
            }
        }

        #pragma unroll
        for (int j = 0; j < 8; j++) {
            uint32_t brow = base + P_WH
                + (uint32_t)(nbase + 8 * j + (L & 7)) * PS + ((L >> 3) & 3) * 16;
            uint32_t bh[4], bl[4];
            ldsm_x4(bh, brow);
            ldsm_x4(bl, brow + (P_WL - P_WH));
            #pragma unroll
            for (int ks = 0; ks < 2; ks++) {
                #pragma unroll
                for (int mt = 0; mt < 2; mt++) {
                    mma_bf16(c[mt][j], ah[mt][ks], bh + 2 * ks);
                    mma_bf16(c[mt][j], al[mt][ks], bh + 2 * ks);
                    mma_bf16(c[mt][j], ah[mt][ks], bl + 2 * ks);
                }
            }
        }
        __syncthreads();
    }

    // Epilogue: split fp32 accum -> bf16 hi/lo stores
    #pragma unroll
    for (int mt = 0; mt < 2; mt++) {
        int r0 = m0 + mrow + mt * 16 + (L >> 2);
        #pragma unroll
        for (int j = 0; j < 8; j++) {
            int cc = nbase + 8 * j + (L & 3) * 2;
            uint32_t h, l;
            split2(c[mt][j][0], c[mt][j][1], h, l);
            *(uint32_t*)&out_hi[(size_t)r0 * HSq + cc] = h;
            *(uint32_t*)&out_lo[(size_t)r0 * HSq + cc] = l;
            split2(c[mt][j][2], c[mt][j][3], h, l);
            *(uint32_t*)&out_hi[(size_t)(r0 + 8) * HSq + cc] = h;
            *(uint32_t*)&out_lo[(size_t)(r0 + 8) * HSq + cc] = l;
        }
    }
}

// ---------------------------------------------------------------------------
// Kernel 2: causal flash attention, HMMA. K double-buffered, V single-buffered.
// Grid (32 q-tiles, 8 batch) = 256 blocks, heavy-first (qt = 31 - bx).
// Block 128 (4 warps), 2 CTAs/SM resident -> cross-CTA latency hiding.
// ---------------------------------------------------------------------------
#define KV_ROWB 272                        // 128 bf16 data + 8 pad
#define KTILE   (64 * KV_ROWB)             // 17408
#define A_KH0   0
#define A_KL0   (1 * KTILE)
#define A_KH1   (2 * KTILE)
#define A_KL1   (3 * KTILE)
#define A_VH    (4 * KTILE)
#define A_VL    (5 * KTILE)
#define ATTN_SMEM (6 * KTILE)              // 104448

__global__ __launch_bounds__(128, 2) void attn_mma_kernel(float* __restrict__ out)
{
    extern __shared__ __align__(16) char smc[];
    const uint32_t sb = smem_u32(smc);
    const int tid = threadIdx.x;
    const int w   = tid >> 5;
    const int L   = tid & 31;
    const int b   = blockIdx.y;
    const int qt  = 31 - blockIdx.x;      // heavy-first
    const int q0  = qt * 64;

    const __nv_bfloat16* qh_g = g_q_hi + (size_t)b * Tq * HSq;
    const __nv_bfloat16* ql_g = g_q_lo + (size_t)b * Tq * HSq;
    const __nv_bfloat16* kh_g = g_k_hi + (size_t)b * Tq * HSq;
    const __nv_bfloat16* kl_g = g_k_lo + (size_t)b * Tq * HSq;
    const __nv_bfloat16* vh_g = g_v_hi + (size_t)b * Tq * HSq;
    const __nv_bfloat16* vl_g = g_v_lo + (size_t)b * Tq * HSq;

    const int lr = L >> 2;
    const int lc = (L & 3) * 2;

    auto prefetch_k = [&](int k0, int buf) {
        uint32_t kh = sb + (buf ? A_KH1 : A_KH0);
        uint32_t kl = sb + (buf ? A_KL1 : A_KL0);
        #pragma unroll
        for (int i = 0; i < 8; i++) {
            int idx = tid + i * 128;
            int r = idx >> 4, q = idx & 15;
            uint32_t d = r * KV_ROWB + q * 16;
            size_t so = (size_t)(k0 + r) * HSq + q * 8;
            cp16(kh + d, kh_g + so);
            cp16(kl + d, kl_g + so);
        }
    };
    auto prefetch_v = [&](int k0) {
        #pragma unroll
        for (int i = 0; i < 8; i++) {
            int idx = tid + i * 128;
            int r = idx >> 4, q = idx & 15;
            uint32_t d = r * KV_ROWB + q * 16;
            size_t so = (size_t)(k0 + r) * HSq + q * 8;
            cp16(sb + A_VH + d, vh_g + so);
            cp16(sb + A_VL + d, vl_g + so);
        }
    };

    // Q fragments (pre-scaled, pre-split) straight from gmem
    uint32_t qh[8][4], ql[8][4];
    #pragma unroll
    for (int s = 0; s < 8; s++)
        #pragma unroll
        for (int i = 0; i < 4; i++) {
            int rr = q0 + 16 * w + lr + 8 * (i & 1);
            int cc = 16 * s + lc + 8 * (i >> 1);
            qh[s][i] = *(const uint32_t*)&qh_g[(size_t)rr * HSq + cc];
            ql[s][i] = *(const uint32_t*)&ql_g[(size_t)rr * HSq + cc];
        }

    float o[16][4];
    #pragma unroll
    for (int j = 0; j < 16; j++)
        #pragma unroll
        for (int r = 0; r < 4; r++) o[j][r] = 0.f;
    float m0v = -1e30f, m1v = -1e30f, l0v = 0.f, l1v = 0.f;

    const int ktiles = qt + 1;

    prefetch_k(0, 0); CP_COMMIT();
    prefetch_v(0);    CP_COMMIT();

    for (int kt = 0; kt < ktiles; kt++) {
        CP_WAIT1();           // K(kt) complete (V(kt)/K(kt+1) may pend)
        __syncthreads();
        if (kt + 1 < ktiles) { prefetch_k((kt + 1) * 64, (kt + 1) & 1); CP_COMMIT(); }

        const uint32_t kb_hi = sb + ((kt & 1) ? A_KH1 : A_KH0);

        // S = Q K^T : 8 n-tiles x 4 k-step-pairs (ldsm.x4), 3-term split
        float c[8][4];
        #pragma unroll
        for (int j = 0; j < 8; j++) {
            c[j][0] = c[j][1] = c[j][2] = c[j][3] = 0.f;
            uint32_t rowaddr = kb_hi + (8 * j + (L & 7)) * KV_ROWB + ((L >> 3) & 3) * 16;
            #pragma unroll
            for (int sp = 0; sp < 4; sp++) {
                uint32_t bh[4], bl[4];
                ldsm_x4(bh, rowaddr + 64 * sp);
                ldsm_x4(bl, rowaddr + 64 * sp + KTILE);
                mma_bf16(c[j], qh[2 * sp],     bh);
                mma_bf16(c[j], ql[2 * sp],     bh);
                mma_bf16(c[j], qh[2 * sp],     bl);
                mma_bf16(c[j], qh[2 * sp + 1], bh + 2);
                mma_bf16(c[j], ql[2 * sp + 1], bh + 2);
                mma_bf16(c[j], qh[2 * sp + 1], bl + 2);
            }
        }

        // Causal mask on diagonal tile
        if (kt == qt) {
            int r0 = 16 * w + lr, r1 = r0 + 8;
            #pragma unroll
            for (int j = 0; j < 8; j++) {
                int n0 = 8 * j + lc;
                if (n0 > r0)     c[j][0] = -1e30f;
                if (n0 + 1 > r0) c[j][1] = -1e30f;
                if (n0 > r1)     c[j][2] = -1e30f;
                if (n0 + 1 > r1) c[j][3] = -1e30f;
            }
        }

        // Online softmax
        float mx0 = -1e30f, mx1 = -1e30f;
        #pragma unroll
        for (int j = 0; j < 8; j++) {
            mx0 = fmaxf(mx0, fmaxf(c[j][0], c[j][1]));
            mx1 = fmaxf(mx1, fmaxf(c[j][2], c[j][3]));
        }
        #pragma unroll
        for (int off = 1; off <= 2; off <<= 1) {
            mx0 = fmaxf(mx0, __shfl_xor_sync(0xffffffffu, mx0, off));
            mx1 = fmaxf(mx1, __shfl_xor_sync(0xffffffffu, mx1, off));
        }
        float mn0 = fmaxf(m0v, mx0), mn1 = fmaxf(m1v, mx1);
        float a0 = __expf(m0v - mn0), a1 = __expf(m1v - mn1);
        float rs0 = 0.f, rs1 = 0.f;
        uint32_t phi[8][2], plo[8][2];
        #pragma unroll
        for (int j = 0; j < 8; j++) {
            float p0 = __expf(c[j][0] - mn0);
            float p1 = __expf(c[j][1] - mn0);
            float p2 = __expf(c[j][2] - mn1);
            float p3 = __expf(c[j][3] - mn1);
            rs0 += p0 + p1; rs1 += p2 + p3;
            split2(p0, p1, phi[j][0], plo[j][0]);
            split2(p2, p3, phi[j][1], plo[j][1]);
        }
        #pragma unroll
        for (int off = 1; off <= 2; off <<= 1) {
            rs0 += __shfl_xor_sync(0xffffffffu, rs0, off);
            rs1 += __shfl_xor_sync(0xffffffffu, rs1, off);
        }
        l0v = l0v * a0 + rs0;  m0v = mn0;
        l1v = l1v * a1 + rs1;  m1v = mn1;
        #pragma unroll
        for (int j = 0; j < 16; j++) {
            o[j][0] *= a0; o[j][1] *= a0;
            o[j][2] *= a1; o[j][3] *= a1;
        }

        // Wait for V(kt); then barrier so all threads' copies are visible
        if (kt + 1 < ktiles) { CP_WAIT1(); } else { CP_WAIT0(); }
        __syncthreads();

        // O += P V : ldsm.x4.trans loads two n-tiles at once
        #pragma unroll
        for (int s = 0; s < 4; s++) {
            uint32_t ap[4]  = { phi[2*s][0], phi[2*s][1], phi[2*s+1][0], phi[2*s+1][1] };
            uint32_t alo[4] = { plo[2*s][0], plo[2*s][1], plo[2*s+1][0], plo[2*s+1][1] };
            uint32_t vaddr = sb + A_VH + (16 * s + (L & 15)) * KV_ROWB + (L >> 4) * 16;
            #pragma unroll
            for (int jj = 0; jj < 16; jj += 2) {
                uint32_t bh[4], bl[4];
                ldsm_x4_t(bh, vaddr + 16 * jj);
                ldsm_x4_t(bl, vaddr + 16 * jj + KTILE);
                mma_bf16(o[jj],     ap,  bh);
                mma_bf16(o[jj],     alo, bh);
                mma_bf16(o[jj],     ap,  bl);
                mma_bf16(o[jj + 1], ap,  bh + 2);
                mma_bf16(o[jj + 1], alo, bh + 2);
                mma_bf16(o[jj + 1], ap,  bl + 2);
            }
        }

        // All warps done reading V -> safe to overwrite with V(kt+1)
        __syncthreads();
        if (kt + 1 < ktiles) { prefetch_v((kt + 1) * 64); CP_COMMIT(); }
    }

    // Epilogue: normalize + store fp32
    float inv0 = __frcp_rn(l0v), inv1 = __frcp_rn(l1v);
    int r0 = q0 + 16 * w + lr;
    #pragma unroll
    for (int jj = 0; jj < 16; jj++) {
        int cc = 8 * jj + lc;
        *(float2*)&out[((size_t)b * Tq + r0) * HSq + cc] =
            make_float2(o[jj][0] * inv0, o[jj][1] * inv0);
        *(float2*)&out[((size_t)b * Tq + r0 + 8) * HSq + cc] =
            make_float2(o[jj][2] * inv1, o[jj][3] * inv1);
    }
}

// ---------------------------------------------------------------------------
extern "C" void kernel_launch(void* const* d_in, const int* in_sizes, int n_in,
                              void* d_out, int out_size)
{
    const float* x  = (const float*)d_in[0];
    const float* Wq = (const float*)d_in[1];
    const float* Wk = (const float*)d_in[2];
    const float* Wv = (const float*)d_in[3];
    float* out = (float*)d_out;

    cudaFuncSetAttribute(proj_mma_kernel, cudaFuncAttributeMaxDynamicSharedMemorySize,
                         PROJ_SMEM);
    cudaFuncSetAttribute(attn_mma_kernel, cudaFuncAttributeMaxDynamicSharedMemorySize,
                         ATTN_SMEM);

    prep_x_kernel<<<BT * Dq / (256 * 8), 256>>>(x);

    dim3 wgrid(Dq / 32, NTOT / 32);
    prep_w_kernel<<<wgrid, dim3(32, 8)>>>(Wq, Wk, Wv);

    dim3 pgrid(BT / 128, 3);
    proj_mma_kernel<<<pgrid, 256, PROJ_SMEM>>>();

    dim3 agrid(32, Bq);
    attn_mma_kernel<<<agrid, 128, ATTN_SMEM>>>(out);
}

// round 9
// speedup vs baseline: 1.2345x; 1.2345x over previous
#include <cuda_runtime.h>
#include <cuda_bf16.h>
#include <math.h>
#include <cstdint>

#define Bq   8
#define Tq   2048
#define Dq   1024
#define HSq  128
#define BT   (Bq * Tq)        // 16384 rows
#define NTOT 384              // 3 * HS

// Scratch (device globals — no allocs allowed). bf16 hi/lo split storage.
__device__ __align__(256) __nv_bfloat16 g_x_hi[BT * Dq];
__device__ __align__(256) __nv_bfloat16 g_x_lo[BT * Dq];
__device__ __align__(256) __nv_bfloat16 g_wt_hi[NTOT * Dq];   // W^T, K-major (Wq pre-scaled)
__device__ __align__(256) __nv_bfloat16 g_wt_lo[NTOT * Dq];
__device__ __align__(256) __nv_bfloat16 g_q_hi[BT * HSq];
__device__ __align__(256) __nv_bfloat16 g_q_lo[BT * HSq];
__device__ __align__(256) __nv_bfloat16 g_k_hi[BT * HSq];
__device__ __align__(256) __nv_bfloat16 g_k_lo[BT * HSq];
__device__ __align__(256) __nv_bfloat16 g_v_hi[BT * HSq];
__device__ __align__(256) __nv_bfloat16 g_v_lo[BT * HSq];

// Split-KV partials: [b][qt][part][64][128] fp32 + per-row m,l
__device__ __align__(256) float g_po[Bq * 32 * 2 * 64 * 128];   // 16 MB
__device__ __align__(256) float g_pm[Bq * 32 * 2 * 64];
__device__ __align__(256) float g_pl[Bq * 32 * 2 * 64];

// Chunk LUT (48 chunks per batch), heavy-first (cnt descending).
// qt, kt0 (in 64-row tiles), cnt (tiles)
__device__ const int c_qt[48]  = {15,16,17,18,19,20,21,22,23,24,25,26,27,28,29,30,31,31,
                                  14,30,13,29,12,28,11,27,10,26, 9,25, 8,24, 7,23,
                                   6,22, 5,21, 4,20, 3,19, 2,18, 1,17, 0,16};
__device__ const int c_k0[48]  = { 0, 0, 0, 0, 0, 0, 0, 0, 0, 0, 0, 0, 0, 0, 0, 0, 0,16,
                                   0,16, 0,16, 0,16, 0,16, 0,16, 0,16, 0,16, 0,16,
                                   0,16, 0,16, 0,16, 0,16, 0,16, 0,16, 0,16};
__device__ const int c_cnt[48] = {16,16,16,16,16,16,16,16,16,16,16,16,16,16,16,16,16,16,
                                  15,15,14,14,13,13,12,12,11,11,10,10, 9, 9, 8, 8,
                                   7, 7, 6, 6, 5, 5, 4, 4, 3, 3, 2, 2, 1, 1};

// ---------------------------------------------------------------------------
// Helpers
// ---------------------------------------------------------------------------
__device__ __forceinline__ void mma_bf16(float* c, const uint32_t* a, const uint32_t* b) {
    asm volatile(
        "mma.sync.aligned.m16n8k16.row.col.f32.bf16.bf16.f32 "
        "{%0,%1,%2,%3}, {%4,%5,%6,%7}, {%8,%9}, {%0,%1,%2,%3};"
        : "+f"(c[0]), "+f"(c[1]), "+f"(c[2]), "+f"(c[3])
        : "r"(a[0]), "r"(a[1]), "r"(a[2]), "r"(a[3]), "r"(b[0]), "r"(b[1]));
}
__device__ __forceinline__ void ldsm_x4(uint32_t* r, uint32_t addr) {
    asm volatile("ldmatrix.sync.aligned.m8n8.x4.shared.b16 {%0,%1,%2,%3}, [%4];"
                 : "=r"(r[0]), "=r"(r[1]), "=r"(r[2]), "=r"(r[3]) : "r"(addr));
}
__device__ __forceinline__ void ldsm_x4_t(uint32_t* r, uint32_t addr) {
    asm volatile("ldmatrix.sync.aligned.m8n8.x4.trans.shared.b16 {%0,%1,%2,%3}, [%4];"
                 : "=r"(r[0]), "=r"(r[1]), "=r"(r[2]), "=r"(r[3]) : "r"(addr));
}
__device__ __forceinline__ uint32_t smem_u32(const void* p) {
    uint32_t a;
    asm("{ .reg .u64 t; cvta.to.shared.u64 t, %1; cvt.u32.u64 %0, t; }"
        : "=r"(a) : "l"(p));
    return a;
}
__device__ __forceinline__ void cp16(uint32_t dst, const void* src) {
    asm volatile("cp.async.cg.shared.global [%0], [%1], 16;" :: "r"(dst), "l"(src));
}
#define CP_COMMIT() asm volatile("cp.async.commit_group;" ::: "memory")
#define CP_WAIT0()  asm volatile("cp.async.wait_group 0;" ::: "memory")
#define CP_WAIT1()  asm volatile("cp.async.wait_group 1;" ::: "memory")

// split pair of floats into packed bf16 hi/lo
__device__ __forceinline__ void split2(float v0, float v1, uint32_t& hi, uint32_t& lo) {
    __nv_bfloat16 h0 = __float2bfloat16_rn(v0);
    __nv_bfloat16 h1 = __float2bfloat16_rn(v1);
    float l0 = v0 - __bfloat162float(h0);
    float l1 = v1 - __bfloat162float(h1);
    hi = (uint32_t)__bfloat16_as_ushort(h0) | ((uint32_t)__bfloat16_as_ushort(h1) << 16);
    __nv_bfloat16 g0 = __float2bfloat16_rn(l0);
    __nv_bfloat16 g1 = __float2bfloat16_rn(l1);
    lo = (uint32_t)__bfloat16_as_ushort(g0) | ((uint32_t)__bfloat16_as_ushort(g1) << 16);
}

// ---------------------------------------------------------------------------
// Kernel 0a: split x -> bf16 hi/lo. 8 floats per thread.
// ---------------------------------------------------------------------------
__global__ __launch_bounds__(256) void prep_x_kernel(const float* __restrict__ x)
{
    size_t i = ((size_t)blockIdx.x * 256 + threadIdx.x) * 8;
    float4 a = *(const float4*)&x[i];
    float4 b = *(const float4*)&x[i + 4];
    uint32_t h0, l0, h1, l1, h2, l2, h3, l3;
    split2(a.x, a.y, h0, l0); split2(a.z, a.w, h1, l1);
    split2(b.x, b.y, h2, l2); split2(b.z, b.w, h3, l3);
    *(uint4*)&g_x_hi[i] = make_uint4(h0, h1, h2, h3);
    *(uint4*)&g_x_lo[i] = make_uint4(l0, l1, l2, l3);
}

// ---------------------------------------------------------------------------
// Kernel 0b: transpose + split-convert weights (Wq scaled by 128^-0.5).
// ---------------------------------------------------------------------------
__global__ void prep_w_kernel(const float* __restrict__ Wq,
                              const float* __restrict__ Wk,
                              const float* __restrict__ Wv)
{
    __shared__ float t[32][33];
    const int k0 = blockIdx.x * 32;
    const int n0 = blockIdx.y * 32;
    const int slab = n0 >> 7;
    const float* W = (slab == 0) ? Wq : (slab == 1) ? Wk : Wv;
    const float sc = (slab == 0) ? 0.08838834764831845f : 1.0f;
    const int nn0 = n0 & 127;
    const int tx = threadIdx.x, ty = threadIdx.y;

    #pragma unroll
    for (int i = 0; i < 4; i++)
        t[ty * 4 + i][tx] = W[(size_t)(k0 + ty * 4 + i) * HSq + nn0 + tx] * sc;
    __syncthreads();
    #pragma unroll
    for (int i = 0; i < 4; i++) {
        int nr = ty * 4 + i;
        float v = t[tx][nr];
        __nv_bfloat16 hi = __float2bfloat16_rn(v);
        __nv_bfloat16 lo = __float2bfloat16_rn(v - __bfloat162float(hi));
        size_t o = (size_t)(n0 + nr) * Dq + k0 + tx;
        g_wt_hi[o] = hi;
        g_wt_lo[o] = lo;
    }
}

// ---------------------------------------------------------------------------
// Kernel 1: QKV projection, HMMA + cp.async double buffer + ldmatrix frags.
// Grid (128 M-tiles, 3 slabs), block 256 (8 warps, 4x2). BM=128 BN=128 BK=32.
// ---------------------------------------------------------------------------
#define PS      80            // smem row pitch bytes (40 bf16)
#define P_ARR   (128 * PS)    // 10240
#define P_XH    0
#define P_XL    (1 * P_ARR)
#define P_WH    (2 * P_ARR)
#define P_WL    (3 * P_ARR)
#define P_BUF   (4 * P_ARR)   // 40960
#define PROJ_SMEM (2 * P_BUF) // 81920

__global__ __launch_bounds__(256, 2) void proj_mma_kernel()
{
    extern __shared__ __align__(16) char smc[];
    const uint32_t sb = smem_u32(smc);
    const int tid = threadIdx.x;
    const int w   = tid >> 5;
    const int L   = tid & 31;
    const int m0  = blockIdx.x * 128;
    const int nt  = blockIdx.y;                   // 0:q 1:k 2:v
    __nv_bfloat16* out_hi = (nt == 0) ? g_q_hi : (nt == 1) ? g_k_hi : g_v_hi;
    __nv_bfloat16* out_lo = (nt == 0) ? g_q_lo : (nt == 1) ? g_k_lo : g_v_lo;

    const __nv_bfloat16* whi = g_wt_hi + (size_t)nt * HSq * Dq;
    const __nv_bfloat16* wlo = g_wt_lo + (size_t)nt * HSq * Dq;
    const __nv_bfloat16* xhi = g_x_hi + (size_t)m0 * Dq;
    const __nv_bfloat16* xlo = g_x_lo + (size_t)m0 * Dq;

    const int mrow  = (w & 3) * 32;
    const int nbase = (w >> 2) * 64;

    float c[2][8][4];
    #pragma unroll
    for (int mt = 0; mt < 2; mt++)
        #pragma unroll
        for (int j = 0; j < 8; j++)
            #pragma unroll
            for (int r = 0; r < 4; r++) c[mt][j][r] = 0.f;

    auto prefetch = [&](int ch, uint32_t bb) {
        const int kb = ch * 32;
        #pragma unroll
        for (int i = 0; i < 2; i++) {
            int idx = tid + i * 256;
            int r = idx >> 2, q = idx & 3;
            uint32_t d = bb + r * PS + q * 16;
            cp16(d + P_XH, xhi + (size_t)r * Dq + kb + q * 8);
            cp16(d + P_XL, xlo + (size_t)r * Dq + kb + q * 8);
            cp16(d + P_WH, whi + (size_t)r * Dq + kb + q * 8);
            cp16(d + P_WL, wlo + (size_t)r * Dq + kb + q * 8);
        }
    };

    prefetch(0, sb);
    CP_COMMIT();

    for (int ch = 0; ch < Dq / 32; ch++) {
        if (ch + 1 < Dq / 32) prefetch(ch + 1, sb + ((ch + 1) & 1) * P_BUF);
        CP_COMMIT();
        CP_WAIT1();
        __syncthreads();

        const uint32_t base = sb + (ch & 1) * P_BUF;

        // A fragments: ldmatrix.x4, [mt][ks][4] for hi and lo
        uint32_t ah[2][2][4], al[2][2][4];
        #pragma unroll
        for (int mt = 0; mt < 2; mt++) {
            uint32_t arow = base + P_XH
                + (uint32_t)(mrow + mt * 16 + (L & 7) + ((L >> 3) & 1) * 8) * PS
                + (L >> 4) * 16;
            #pragma unroll
            for (int ks = 0; ks < 2; ks++) {
                ldsm_x4(ah[mt][ks], arow + ks * 32);
                ldsm_x4(al[mt][ks], arow + ks * 32 + (P_XL - P_XH));
            }
        }

        #pragma unroll
        for (int j = 0; j < 8; j++) {
            uint32_t brow = base + P_WH
                + (uint32_t)(nbase + 8 * j + (L & 7)) * PS + ((L >> 3) & 3) * 16;
            uint32_t bh[4], bl[4];
            ldsm_x4(bh, brow);
            ldsm_x4(bl, brow + (P_WL - P_WH));
            #pragma unroll
            for (int ks = 0; ks < 2; ks++) {
                #pragma unroll
                for (int mt = 0; mt < 2; mt++) {
                    mma_bf16(c[mt][j], ah[mt][ks], bh + 2 * ks);
                    mma_bf16(c[mt][j], al[mt][ks], bh + 2 * ks);
                    mma_bf16(c[mt][j], ah[mt][ks], bl + 2 * ks);
                }
            }
        }
        __syncthreads();
    }

    // Epilogue: split fp32 accum -> bf16 hi/lo stores
    #pragma unroll
    for (int mt = 0; mt < 2; mt++) {
        int r0 = m0 + mrow + mt * 16 + (L >> 2);
        #pragma unroll
        for (int j = 0; j < 8; j++) {
            int cc = nbase + 8 * j + (L & 3) * 2;
            uint32_t h, l;
            split2(c[mt][j][0], c[mt][j][1], h, l);
            *(uint32_t*)&out_hi[(size_t)r0 * HSq + cc] = h;
            *(uint32_t*)&out_lo[(size_t)r0 * HSq + cc] = l;
            split2(c[mt][j][2], c[mt][j][3], h, l);
            *(uint32_t*)&out_hi[(size_t)(r0 + 8) * HSq + cc] = h;
            *(uint32_t*)&out_lo[(size_t)(r0 + 8) * HSq + cc] = l;
        }
    }
}

// ---------------------------------------------------------------------------
// Kernel 2: split-KV causal flash attention chunk kernel.
// Grid (8 batch, 48 chunks heavy-first). Block 128 (4 warps), 2 CTAs/SM.
// Each block computes a partial (O, m, l) over <=16 KV tiles of one q-tile.
// ---------------------------------------------------------------------------
#define KV_ROWB 272                        // 128 bf16 data + 8 pad
#define KTILE   (64 * KV_ROWB)             // 17408
#define A_KH0   0
#define A_KL0   (1 * KTILE)
#define A_KH1   (2 * KTILE)
#define A_KL1   (3 * KTILE)
#define A_VH    (4 * KTILE)
#define A_VL    (5 * KTILE)
#define ATTN_SMEM (6 * KTILE)              // 104448

__global__ __launch_bounds__(128, 2) void attn_mma_kernel()
{
    extern __shared__ __align__(16) char smc[];
    const uint32_t sb = smem_u32(smc);
    const int tid = threadIdx.x;
    const int w   = tid >> 5;
    const int L   = tid & 31;
    const int b   = blockIdx.x;
    const int cid = blockIdx.y;
    const int qt  = c_qt[cid];
    const int kt0 = c_k0[cid];
    const int cnt = c_cnt[cid];
    const int q0  = qt * 64;

    const __nv_bfloat16* qh_g = g_q_hi + (size_t)b * Tq * HSq;
    const __nv_bfloat16* ql_g = g_q_lo + (size_t)b * Tq * HSq;
    const __nv_bfloat16* kh_g = g_k_hi + (size_t)b * Tq * HSq;
    const __nv_bfloat16* kl_g = g_k_lo + (size_t)b * Tq * HSq;
    const __nv_bfloat16* vh_g = g_v_hi + (size_t)b * Tq * HSq;
    const __nv_bfloat16* vl_g = g_v_lo + (size_t)b * Tq * HSq;

    const int lr = L >> 2;
    const int lc = (L & 3) * 2;

    auto prefetch_k = [&](int krow, int buf) {
        uint32_t kh = sb + (buf ? A_KH1 : A_KH0);
        uint32_t kl = sb + (buf ? A_KL1 : A_KL0);
        #pragma unroll
        for (int i = 0; i < 8; i++) {
            int idx = tid + i * 128;
            int r = idx >> 4, q = idx & 15;
            uint32_t d = r * KV_ROWB + q * 16;
            size_t so = (size_t)(krow + r) * HSq + q * 8;
            cp16(kh + d, kh_g + so);
            cp16(kl + d, kl_g + so);
        }
    };
    auto prefetch_v = [&](int krow) {
        #pragma unroll
        for (int i = 0; i < 8; i++) {
            int idx = tid + i * 128;
            int r = idx >> 4, q = idx & 15;
            uint32_t d = r * KV_ROWB + q * 16;
            size_t so = (size_t)(krow + r) * HSq + q * 8;
            cp16(sb + A_VH + d, vh_g + so);
            cp16(sb + A_VL + d, vl_g + so);
        }
    };

    // Q fragments (pre-scaled, pre-split) straight from gmem
    uint32_t qh[8][4], ql[8][4];
    #pragma unroll
    for (int s = 0; s < 8; s++)
        #pragma unroll
        for (int i = 0; i < 4; i++) {
            int rr = q0 + 16 * w + lr + 8 * (i & 1);
            int cc = 16 * s + lc + 8 * (i >> 1);
            qh[s][i] = *(const uint32_t*)&qh_g[(size_t)rr * HSq + cc];
            ql[s][i] = *(const uint32_t*)&ql_g[(size_t)rr * HSq + cc];
        }

    float o[16][4];
    #pragma unroll
    for (int j = 0; j < 16; j++)
        #pragma unroll
        for (int r = 0; r < 4; r++) o[j][r] = 0.f;
    float m0v = -1e30f, m1v = -1e30f, l0v = 0.f, l1v = 0.f;

    prefetch_k(kt0 * 64, 0); CP_COMMIT();
    prefetch_v(kt0 * 64);    CP_COMMIT();

    for (int t = 0; t < cnt; t++) {
        const int tile = kt0 + t;
        CP_WAIT1();           // K(t) complete
        __syncthreads();
        if (t + 1 < cnt) { prefetch_k((tile + 1) * 64, (t + 1) & 1); CP_COMMIT(); }

        const uint32_t kb_hi = sb + ((t & 1) ? A_KH1 : A_KH0);

        // S = Q K^T : 8 n-tiles x 4 k-step-pairs (ldsm.x4), 3-term split
        float c[8][4];
        #pragma unroll
        for (int j = 0; j < 8; j++) {
            c[j][0] = c[j][1] = c[j][2] = c[j][3] = 0.f;
            uint32_t rowaddr = kb_hi + (8 * j + (L & 7)) * KV_ROWB + ((L >> 3) & 3) * 16;
            #pragma unroll
            for (int sp = 0; sp < 4; sp++) {
                uint32_t bh[4], bl[4];
                ldsm_x4(bh, rowaddr + 64 * sp);
                ldsm_x4(bl, rowaddr + 64 * sp + KTILE);
                mma_bf16(c[j], qh[2 * sp],     bh);
                mma_bf16(c[j], ql[2 * sp],     bh);
                mma_bf16(c[j], qh[2 * sp],     bl);
                mma_bf16(c[j], qh[2 * sp + 1], bh + 2);
                mma_bf16(c[j], ql[2 * sp + 1], bh + 2);
                mma_bf16(c[j], qh[2 * sp + 1], bl + 2);
            }
        }

        // Causal mask on diagonal tile
        if (tile == qt) {
            int r0 = 16 * w + lr, r1 = r0 + 8;
            #pragma unroll
            for (int j = 0; j < 8; j++) {
                int n0 = 8 * j + lc;
                if (n0 > r0)     c[j][0] = -1e30f;
                if (n0 + 1 > r0) c[j][1] = -1e30f;
                if (n0 > r1)     c[j][2] = -1e30f;
                if (n0 + 1 > r1) c[j][3] = -1e30f;
            }
        }

        // Online softmax
        float mx0 = -1e30f, mx1 = -1e30f;
        #pragma unroll
        for (int j = 0; j < 8; j++) {
            mx0 = fmaxf(mx0, fmaxf(c[j][0], c[j][1]));
            mx1 = fmaxf(mx1, fmaxf(c[j][2], c[j][3]));
        }
        #pragma unroll
        for (int off = 1; off <= 2; off <<= 1) {
            mx0 = fmaxf(mx0, __shfl_xor_sync(0xffffffffu, mx0, off));
            mx1 = fmaxf(mx1, __shfl_xor_sync(0xffffffffu, mx1, off));
        }
        float mn0 = fmaxf(m0v, mx0), mn1 = fmaxf(m1v, mx1);
        float a0 = __expf(m0v - mn0), a1 = __expf(m1v - mn1);
        float rs0 = 0.f, rs1 = 0.f;
        uint32_t phi[8][2], plo[8][2];
        #pragma unroll
        for (int j = 0; j < 8; j++) {
            float p0 = __expf(c[j][0] - mn0);
            float p1 = __expf(c[j][1] - mn0);
            float p2 = __expf(c[j][2] - mn1);
            float p3 = __expf(c[j][3] - mn1);
            rs0 += p0 + p1; rs1 += p2 + p3;
            split2(p0, p1, phi[j][0], plo[j][0]);
            split2(p2, p3, phi[j][1], plo[j][1]);
        }
        #pragma unroll
        for (int off = 1; off <= 2; off <<= 1) {
            rs0 += __shfl_xor_sync(0xffffffffu, rs0, off);
            rs1 += __shfl_xor_sync(0xffffffffu, rs1, off);
        }
        l0v = l0v * a0 + rs0;  m0v = mn0;
        l1v = l1v * a1 + rs1;  m1v = mn1;
        #pragma unroll
        for (int j = 0; j < 16; j++) {
            o[j][0] *= a0; o[j][1] *= a0;
            o[j][2] *= a1; o[j][3] *= a1;
        }

        // Wait for V(t); then barrier so all threads' copies are visible
        if (t + 1 < cnt) { CP_WAIT1(); } else { CP_WAIT0(); }
        __syncthreads();

        // O += P V : ldsm.x4.trans loads two n-tiles at once
        #pragma unroll
        for (int s = 0; s < 4; s++) {
            uint32_t ap[4]  = { phi[2*s][0], phi[2*s][1], phi[2*s+1][0], phi[2*s+1][1] };
            uint32_t alo[4] = { plo[2*s][0], plo[2*s][1], plo[2*s+1][0], plo[2*s+1][1] };
            uint32_t vaddr = sb + A_VH + (16 * s + (L & 15)) * KV_ROWB + (L >> 4) * 16;
            #pragma unroll
            for (int jj = 0; jj < 16; jj += 2) {
                uint32_t bh[4], bl[4];
                ldsm_x4_t(bh, vaddr + 16 * jj);
                ldsm_x4_t(bl, vaddr + 16 * jj + KTILE);
                mma_bf16(o[jj],     ap,  bh);
                mma_bf16(o[jj],     alo, bh);
                mma_bf16(o[jj],     ap,  bl);
                mma_bf16(o[jj + 1], ap,  bh + 2);
                mma_bf16(o[jj + 1], alo, bh + 2);
                mma_bf16(o[jj + 1], ap,  bl + 2);
            }
        }

        // All warps done reading V -> safe to overwrite with V(t+1)
        __syncthreads();
        if (t + 1 < cnt) { prefetch_v((tile + 1) * 64); CP_COMMIT(); }
    }

    // Epilogue: store UNNORMALIZED partial O plus (m, l)
    const int part = (kt0 == 0) ? 0 : 1;
    const size_t pb = (((size_t)b * 32 + qt) * 2 + part) * (64 * 128);
    const size_t mb = (((size_t)b * 32 + qt) * 2 + part) * 64;
    int r0 = 16 * w + lr;
    #pragma unroll
    for (int jj = 0; jj < 16; jj++) {
        int cc = 8 * jj + lc;
        *(float2*)&g_po[pb + (size_t)r0 * 128 + cc] = make_float2(o[jj][0], o[jj][1]);
        *(float2*)&g_po[pb + (size_t)(r0 + 8) * 128 + cc] = make_float2(o[jj][2], o[jj][3]);
    }
    if ((L & 3) == 0) {
        g_pm[mb + r0] = m0v;  g_pl[mb + r0] = l0v;
        g_pm[mb + r0 + 8] = m1v;  g_pl[mb + r0 + 8] = l1v;
    }
}

// ---------------------------------------------------------------------------
// Kernel 3: merge partials -> final normalized output.
// Grid (32 q-tiles, 8 batch), block 256. qt<16: 1 part; qt>=16: 2 parts.
// ---------------------------------------------------------------------------
__global__ __launch_bounds__(256) void merge_kernel(float* __restrict__ out)
{
    const int qt = blockIdx.x;
    const int b  = blockIdx.y;
    const int tid = threadIdx.x;
    const size_t base0 = (((size_t)b * 32 + qt) * 2 + 0) * (64 * 128);
    const size_t base1 = base0 + 64 * 128;
    const size_t mb0 = (((size_t)b * 32 + qt) * 2 + 0) * 64;
    const size_t mb1 = mb0 + 64;
    const bool two = (qt >= 16);

    #pragma unroll
    for (int i = 0; i < 8; i++) {
        int idx = tid + i * 256;        // float4 index, 2048 total
        int off = idx * 4;
        int row = off >> 7;
        int col = off & 127;
        float4 a = *(const float4*)&g_po[base0 + off];
        float mA = g_pm[mb0 + row], lA = g_pl[mb0 + row];
        float4 res;
        if (two) {
            float4 bb = *(const float4*)&g_po[base1 + off];
            float mB = g_pm[mb1 + row], lB = g_pl[mb1 + row];
            float m = fmaxf(mA, mB);
            float wA = __expf(mA - m), wB = __expf(mB - m);
            float inv = __frcp_rn(lA * wA + lB * wB);
            res = make_float4((a.x * wA + bb.x * wB) * inv,
                              (a.y * wA + bb.y * wB) * inv,
                              (a.z * wA + bb.z * wB) * inv,
                              (a.w * wA + bb.w * wB) * inv);
        } else {
            float inv = __frcp_rn(lA);
            res = make_float4(a.x * inv, a.y * inv, a.z * inv, a.w * inv);
        }
        *(float4*)&out[((size_t)b * Tq + qt * 64 + row) * HSq + col] = res;
    }
}

// ---------------------------------------------------------------------------
extern "C" void kernel_launch(void* const* d_in, const int* in_sizes, int n_in,
                              void* d_out, int out_size)
{
    const float* x  = (const float*)d_in[0];
    const float* Wq = (const float*)d_in[1];
    const float* Wk = (const float*)d_in[2];
    const float* Wv = (const float*)d_in[3];
    float* out = (float*)d_out;

    cudaFuncSetAttribute(proj_mma_kernel, cudaFuncAttributeMaxDynamicSharedMemorySize,
                         PROJ_SMEM);
    cudaFuncSetAttribute(attn_mma_kernel, cudaFuncAttributeMaxDynamicSharedMemorySize,
                         ATTN_SMEM);

    prep_x_kernel<<<BT * Dq / (256 * 8), 256>>>(x);

    dim3 wgrid(Dq / 32, NTOT / 32);
    prep_w_kernel<<<wgrid, dim3(32, 8)>>>(Wq, Wk, Wv);

    dim3 pgrid(BT / 128, 3);
    proj_mma_kernel<<<pgrid, 256, PROJ_SMEM>>>();

    dim3 agrid(Bq, 48);
    attn_mma_kernel<<<agrid, 128, ATTN_SMEM>>>();

    dim3 mgrid(32, Bq);
    merge_kernel<<<mgrid, 256>>>(out);
}

// round 10
// speedup vs baseline: 1.4858x; 1.2036x over previous
#include <cuda_runtime.h>
#include <cuda_bf16.h>
#include <cuda_fp16.h>
#include <math.h>
#include <cstdint>

#define Bq   8
#define Tq   2048
#define Dq   1024
#define HSq  128
#define BT   (Bq * Tq)        // 16384 rows
#define NTOT 384              // 3 * HS

// Scratch (device globals — no allocs allowed).
__device__ __align__(256) __half g_x_hi[BT * Dq];            // x split, fp16
__device__ __align__(256) __half g_x_lo[BT * Dq];
__device__ __align__(256) __half g_wt_h[NTOT * Dq];          // W^T fp16 (Wq pre-scaled)
__device__ __align__(256) __nv_bfloat16 g_q_hi[BT * HSq];    // q/k/v split, bf16 (3-term attn)
__device__ __align__(256) __nv_bfloat16 g_q_lo[BT * HSq];
__device__ __align__(256) __nv_bfloat16 g_k_hi[BT * HSq];
__device__ __align__(256) __nv_bfloat16 g_k_lo[BT * HSq];
__device__ __align__(256) __nv_bfloat16 g_v_hi[BT * HSq];
__device__ __align__(256) __nv_bfloat16 g_v_lo[BT * HSq];

// Split-KV partials: [b][qt][part][64][128] fp32 + per-row m,l (base-2 logits)
__device__ __align__(256) float g_po[Bq * 32 * 2 * 64 * 128];   // 16 MB
__device__ __align__(256) float g_pm[Bq * 32 * 2 * 64];
__device__ __align__(256) float g_pl[Bq * 32 * 2 * 64];

// Chunk LUT (48 chunks per batch), heavy-first (cnt descending).
__device__ const int c_qt[48]  = {15,16,17,18,19,20,21,22,23,24,25,26,27,28,29,30,31,31,
                                  14,30,13,29,12,28,11,27,10,26, 9,25, 8,24, 7,23,
                                   6,22, 5,21, 4,20, 3,19, 2,18, 1,17, 0,16};
__device__ const int c_k0[48]  = { 0, 0, 0, 0, 0, 0, 0, 0, 0, 0, 0, 0, 0, 0, 0, 0, 0,16,
                                   0,16, 0,16, 0,16, 0,16, 0,16, 0,16, 0,16, 0,16,
                                   0,16, 0,16, 0,16, 0,16, 0,16, 0,16, 0,16};
__device__ const int c_cnt[48] = {16,16,16,16,16,16,16,16,16,16,16,16,16,16,16,16,16,16,
                                  15,15,14,14,13,13,12,12,11,11,10,10, 9, 9, 8, 8,
                                   7, 7, 6, 6, 5, 5, 4, 4, 3, 3, 2, 2, 1, 1};

// ---------------------------------------------------------------------------
// Helpers
// ---------------------------------------------------------------------------
__device__ __forceinline__ void mma_bf16(float* c, const uint32_t* a, const uint32_t* b) {
    asm volatile(
        "mma.sync.aligned.m16n8k16.row.col.f32.bf16.bf16.f32 "
        "{%0,%1,%2,%3}, {%4,%5,%6,%7}, {%8,%9}, {%0,%1,%2,%3};"
        : "+f"(c[0]), "+f"(c[1]), "+f"(c[2]), "+f"(c[3])
        : "r"(a[0]), "r"(a[1]), "r"(a[2]), "r"(a[3]), "r"(b[0]), "r"(b[1]));
}
__device__ __forceinline__ void mma_f16(float* c, const uint32_t* a, const uint32_t* b) {
    asm volatile(
        "mma.sync.aligned.m16n8k16.row.col.f32.f16.f16.f32 "
        "{%0,%1,%2,%3}, {%4,%5,%6,%7}, {%8,%9}, {%0,%1,%2,%3};"
        : "+f"(c[0]), "+f"(c[1]), "+f"(c[2]), "+f"(c[3])
        : "r"(a[0]), "r"(a[1]), "r"(a[2]), "r"(a[3]), "r"(b[0]), "r"(b[1]));
}
__device__ __forceinline__ void ldsm_x4(uint32_t* r, uint32_t addr) {
    asm volatile("ldmatrix.sync.aligned.m8n8.x4.shared.b16 {%0,%1,%2,%3}, [%4];"
                 : "=r"(r[0]), "=r"(r[1]), "=r"(r[2]), "=r"(r[3]) : "r"(addr));
}
__device__ __forceinline__ void ldsm_x4_t(uint32_t* r, uint32_t addr) {
    asm volatile("ldmatrix.sync.aligned.m8n8.x4.trans.shared.b16 {%0,%1,%2,%3}, [%4];"
                 : "=r"(r[0]), "=r"(r[1]), "=r"(r[2]), "=r"(r[3]) : "r"(addr));
}
__device__ __forceinline__ uint32_t smem_u32(const void* p) {
    uint32_t a;
    asm("{ .reg .u64 t; cvta.to.shared.u64 t, %1; cvt.u32.u64 %0, t; }"
        : "=r"(a) : "l"(p));
    return a;
}
__device__ __forceinline__ void cp16(uint32_t dst, const void* src) {
    asm volatile("cp.async.cg.shared.global [%0], [%1], 16;" :: "r"(dst), "l"(src));
}
#define CP_COMMIT() asm volatile("cp.async.commit_group;" ::: "memory")
#define CP_WAIT0()  asm volatile("cp.async.wait_group 0;" ::: "memory")
#define CP_WAIT1()  asm volatile("cp.async.wait_group 1;" ::: "memory")

// bf16 hi/lo split (cvt-based, fewer instructions)
__device__ __forceinline__ void split2(float v0, float v1, uint32_t& hi, uint32_t& lo) {
    uint32_t h;
    asm("cvt.rn.bf16x2.f32 %0, %1, %2;" : "=r"(h) : "f"(v1), "f"(v0));
    float f0 = __uint_as_float(h << 16);
    float f1 = __uint_as_float(h & 0xffff0000u);
    uint32_t l;
    float r0 = v0 - f0, r1 = v1 - f1;
    asm("cvt.rn.bf16x2.f32 %0, %1, %2;" : "=r"(l) : "f"(r1), "f"(r0));
    hi = h; lo = l;
}
// fp16 hi/lo split
__device__ __forceinline__ void split2h(float v0, float v1, uint32_t& hi, uint32_t& lo) {
    __half2 h2 = __floats2half2_rn(v0, v1);
    float2 f = __half22float2(h2);
    __half2 l2 = __floats2half2_rn(v0 - f.x, v1 - f.y);
    hi = *(uint32_t*)&h2;
    lo = *(uint32_t*)&l2;
}

// ---------------------------------------------------------------------------
// Kernel 0a: split x -> fp16 hi/lo. 8 floats per thread.
// ---------------------------------------------------------------------------
__global__ __launch_bounds__(256) void prep_x_kernel(const float* __restrict__ x)
{
    size_t i = ((size_t)blockIdx.x * 256 + threadIdx.x) * 8;
    float4 a = *(const float4*)&x[i];
    float4 b = *(const float4*)&x[i + 4];
    uint32_t h0, l0, h1, l1, h2, l2, h3, l3;
    split2h(a.x, a.y, h0, l0); split2h(a.z, a.w, h1, l1);
    split2h(b.x, b.y, h2, l2); split2h(b.z, b.w, h3, l3);
    *(uint4*)&g_x_hi[i] = make_uint4(h0, h1, h2, h3);
    *(uint4*)&g_x_lo[i] = make_uint4(l0, l1, l2, l3);
}

// ---------------------------------------------------------------------------
// Kernel 0b: transpose + convert weights to fp16 (Wq scaled by 128^-0.5*log2e).
// ---------------------------------------------------------------------------
__global__ void prep_w_kernel(const float* __restrict__ Wq,
                              const float* __restrict__ Wk,
                              const float* __restrict__ Wv)
{
    __shared__ float t[32][33];
    const int k0 = blockIdx.x * 32;
    const int n0 = blockIdx.y * 32;
    const int slab = n0 >> 7;
    const float* W = (slab == 0) ? Wq : (slab == 1) ? Wk : Wv;
    const float sc = (slab == 0) ? (0.08838834764831845f * 1.4426950408889634f) : 1.0f;
    const int nn0 = n0 & 127;
    const int tx = threadIdx.x, ty = threadIdx.y;

    #pragma unroll
    for (int i = 0; i < 4; i++)
        t[ty * 4 + i][tx] = W[(size_t)(k0 + ty * 4 + i) * HSq + nn0 + tx] * sc;
    __syncthreads();
    #pragma unroll
    for (int i = 0; i < 4; i++) {
        int nr = ty * 4 + i;
        g_wt_h[(size_t)(n0 + nr) * Dq + k0 + tx] = __float2half_rn(t[tx][nr]);
    }
}

// ---------------------------------------------------------------------------
// Kernel 1: QKV projection, fp16 2-term HMMA (x split hi/lo, W single fp16).
// Grid (128 M-tiles, 3 slabs), block 256 (8 warps, 4x2). BM=128 BN=128 BK=32.
// ---------------------------------------------------------------------------
#define PS      80            // smem row pitch bytes (40 fp16)
#define P_ARR   (128 * PS)    // 10240
#define P_XH    0
#define P_XL    (1 * P_ARR)
#define P_WH    (2 * P_ARR)
#define P_BUF   (3 * P_ARR)   // 30720
#define PROJ_SMEM (2 * P_BUF) // 61440

__global__ __launch_bounds__(256, 2) void proj_mma_kernel()
{
    extern __shared__ __align__(16) char smc[];
    const uint32_t sb = smem_u32(smc);
    const int tid = threadIdx.x;
    const int w   = tid >> 5;
    const int L   = tid & 31;
    const int m0  = blockIdx.x * 128;
    const int nt  = blockIdx.y;                   // 0:q 1:k 2:v
    __nv_bfloat16* out_hi = (nt == 0) ? g_q_hi : (nt == 1) ? g_k_hi : g_v_hi;
    __nv_bfloat16* out_lo = (nt == 0) ? g_q_lo : (nt == 1) ? g_k_lo : g_v_lo;

    const __half* wh  = g_wt_h + (size_t)nt * HSq * Dq;
    const __half* xhi = g_x_hi + (size_t)m0 * Dq;
    const __half* xlo = g_x_lo + (size_t)m0 * Dq;

    const int mrow  = (w & 3) * 32;
    const int nbase = (w >> 2) * 64;

    float c[2][8][4];
    #pragma unroll
    for (int mt = 0; mt < 2; mt++)
        #pragma unroll
        for (int j = 0; j < 8; j++)
            #pragma unroll
            for (int r = 0; r < 4; r++) c[mt][j][r] = 0.f;

    auto prefetch = [&](int ch, uint32_t bb) {
        const int kb = ch * 32;
        #pragma unroll
        for (int i = 0; i < 2; i++) {
            int idx = tid + i * 256;
            int r = idx >> 2, q = idx & 3;
            uint32_t d = bb + r * PS + q * 16;
            cp16(d + P_XH, xhi + (size_t)r * Dq + kb + q * 8);
            cp16(d + P_XL, xlo + (size_t)r * Dq + kb + q * 8);
            cp16(d + P_WH, wh  + (size_t)r * Dq + kb + q * 8);
        }
    };

    prefetch(0, sb);
    CP_COMMIT();

    for (int ch = 0; ch < Dq / 32; ch++) {
        if (ch + 1 < Dq / 32) prefetch(ch + 1, sb + ((ch + 1) & 1) * P_BUF);
        CP_COMMIT();
        CP_WAIT1();
        __syncthreads();

        const uint32_t base = sb + (ch & 1) * P_BUF;

        // A fragments (x hi/lo): ldmatrix.x4
        uint32_t ah[2][2][4], al[2][2][4];
        #pragma unroll
        for (int mt = 0; mt < 2; mt++) {
            uint32_t arow = base + P_XH
                + (uint32_t)(mrow + mt * 16 + (L & 7) + ((L >> 3) & 1) * 8) * PS
                + (L >> 4) * 16;
            #pragma unroll
            for (int ks = 0; ks < 2; ks++) {
                ldsm_x4(ah[mt][ks], arow + ks * 32);
                ldsm_x4(al[mt][ks], arow + ks * 32 + (P_XL - P_XH));
            }
        }

        #pragma unroll
        for (int j = 0; j < 8; j++) {
            uint32_t brow = base + P_WH
                + (uint32_t)(nbase + 8 * j + (L & 7)) * PS + ((L >> 3) & 3) * 16;
            uint32_t bh[4];
            ldsm_x4(bh, brow);
            // 2-term: x_hi*W + x_lo*W; interleaved for accumulator distance
            #pragma unroll
            for (int t = 0; t < 2; t++) {
                #pragma unroll
                for (int ks = 0; ks < 2; ks++) {
                    #pragma unroll
                    for (int mt = 0; mt < 2; mt++) {
                        mma_f16(c[mt][j], t ? al[mt][ks] : ah[mt][ks], bh + 2 * ks);
                    }
                }
            }
        }
        __syncthreads();
    }

    // Epilogue: split fp32 accum -> bf16 hi/lo stores (for 3-term bf16 attention)
    #pragma unroll
    for (int mt = 0; mt < 2; mt++) {
        int r0 = m0 + mrow + mt * 16 + (L >> 2);
        #pragma unroll
        for (int j = 0; j < 8; j++) {
            int cc = nbase + 8 * j + (L & 3) * 2;
            uint32_t h, l;
            split2(c[mt][j][0], c[mt][j][1], h, l);
            *(uint32_t*)&out_hi[(size_t)r0 * HSq + cc] = h;
            *(uint32_t*)&out_lo[(size_t)r0 * HSq + cc] = l;
            split2(c[mt][j][2], c[mt][j][3], h, l);
            *(uint32_t*)&out_hi[(size_t)(r0 + 8) * HSq + cc] = h;
            *(uint32_t*)&out_lo[(size_t)(r0 + 8) * HSq + cc] = l;
        }
    }
}

// ---------------------------------------------------------------------------
// Kernel 2: split-KV causal flash attention chunk kernel (3-term bf16).
// Base-2 logits (log2e folded into Wq). Full-range chunks write output direct.
// Grid (8 batch, 48 chunks heavy-first). Block 128 (4 warps), 2 CTAs/SM.
// ---------------------------------------------------------------------------
#define KV_ROWB 272                        // 128 bf16 data + 8 pad
#define KTILE   (64 * KV_ROWB)             // 17408
#define A_KH0   0
#define A_KL0   (1 * KTILE)
#define A_KH1   (2 * KTILE)
#define A_KL1   (3 * KTILE)
#define A_VH    (4 * KTILE)
#define A_VL    (5 * KTILE)
#define ATTN_SMEM (6 * KTILE)              // 104448

__global__ __launch_bounds__(128, 2) void attn_mma_kernel(float* __restrict__ out)
{
    extern __shared__ __align__(16) char smc[];
    const uint32_t sb = smem_u32(smc);
    const int tid = threadIdx.x;
    const int w   = tid >> 5;
    const int L   = tid & 31;
    const int b   = blockIdx.x;
    const int cid = blockIdx.y;
    const int qt  = c_qt[cid];
    const int kt0 = c_k0[cid];
    const int cnt = c_cnt[cid];
    const int q0  = qt * 64;

    const __nv_bfloat16* qh_g = g_q_hi + (size_t)b * Tq * HSq;
    const __nv_bfloat16* ql_g = g_q_lo + (size_t)b * Tq * HSq;
    const __nv_bfloat16* kh_g = g_k_hi + (size_t)b * Tq * HSq;
    const __nv_bfloat16* kl_g = g_k_lo + (size_t)b * Tq * HSq;
    const __nv_bfloat16* vh_g = g_v_hi + (size_t)b * Tq * HSq;
    const __nv_bfloat16* vl_g = g_v_lo + (size_t)b * Tq * HSq;

    const int lr = L >> 2;
    const int lc = (L & 3) * 2;

    auto prefetch_k = [&](int krow, int buf) {
        uint32_t kh = sb + (buf ? A_KH1 : A_KH0);
        uint32_t kl = sb + (buf ? A_KL1 : A_KL0);
        #pragma unroll
        for (int i = 0; i < 8; i++) {
            int idx = tid + i * 128;
            int r = idx >> 4, q = idx & 15;
            uint32_t d = r * KV_ROWB + q * 16;
            size_t so = (size_t)(krow + r) * HSq + q * 8;
            cp16(kh + d, kh_g + so);
            cp16(kl + d, kl_g + so);
        }
    };
    auto prefetch_v = [&](int krow) {
        #pragma unroll
        for (int i = 0; i < 8; i++) {
            int idx = tid + i * 128;
            int r = idx >> 4, q = idx & 15;
            uint32_t d = r * KV_ROWB + q * 16;
            size_t so = (size_t)(krow + r) * HSq + q * 8;
            cp16(sb + A_VH + d, vh_g + so);
            cp16(sb + A_VL + d, vl_g + so);
        }
    };

    // Q fragments (pre-scaled by 128^-0.5*log2e, pre-split)
    uint32_t qh[8][4], ql[8][4];
    #pragma unroll
    for (int s = 0; s < 8; s++)
        #pragma unroll
        for (int i = 0; i < 4; i++) {
            int rr = q0 + 16 * w + lr + 8 * (i & 1);
            int cc = 16 * s + lc + 8 * (i >> 1);
            qh[s][i] = *(const uint32_t*)&qh_g[(size_t)rr * HSq + cc];
            ql[s][i] = *(const uint32_t*)&ql_g[(size_t)rr * HSq + cc];
        }

    float o[16][4];
    #pragma unroll
    for (int j = 0; j < 16; j++)
        #pragma unroll
        for (int r = 0; r < 4; r++) o[j][r] = 0.f;
    float m0v = -1e30f, m1v = -1e30f, l0v = 0.f, l1v = 0.f;

    prefetch_k(kt0 * 64, 0); CP_COMMIT();
    prefetch_v(kt0 * 64);    CP_COMMIT();

    for (int t = 0; t < cnt; t++) {
        const int tile = kt0 + t;
        CP_WAIT1();           // K(t) complete
        __syncthreads();
        if (t + 1 < cnt) { prefetch_k((tile + 1) * 64, (t + 1) & 1); CP_COMMIT(); }

        const uint32_t kb_hi = sb + ((t & 1) ? A_KH1 : A_KH0);

        // S = Q K^T : 3-term split, base-2 logits
        float c[8][4];
        #pragma unroll
        for (int j = 0; j < 8; j++) {
            c[j][0] = c[j][1] = c[j][2] = c[j][3] = 0.f;
            uint32_t rowaddr = kb_hi + (8 * j + (L & 7)) * KV_ROWB + ((L >> 3) & 3) * 16;
            #pragma unroll
            for (int sp = 0; sp < 4; sp++) {
                uint32_t bh[4], bl[4];
                ldsm_x4(bh, rowaddr + 64 * sp);
                ldsm_x4(bl, rowaddr + 64 * sp + KTILE);
                mma_bf16(c[j], qh[2 * sp],     bh);
                mma_bf16(c[j], ql[2 * sp],     bh);
                mma_bf16(c[j], qh[2 * sp],     bl);
                mma_bf16(c[j], qh[2 * sp + 1], bh + 2);
                mma_bf16(c[j], ql[2 * sp + 1], bh + 2);
                mma_bf16(c[j], qh[2 * sp + 1], bl + 2);
            }
        }

        // Causal mask on diagonal tile
        if (tile == qt) {
            int r0 = 16 * w + lr, r1 = r0 + 8;
            #pragma unroll
            for (int j = 0; j < 8; j++) {
                int n0 = 8 * j + lc;
                if (n0 > r0)     c[j][0] = -1e30f;
                if (n0 + 1 > r0) c[j][1] = -1e30f;
                if (n0 > r1)     c[j][2] = -1e30f;
                if (n0 + 1 > r1) c[j][3] = -1e30f;
            }
        }

        // Online softmax (base-2)
        float mx0 = -1e30f, mx1 = -1e30f;
        #pragma unroll
        for (int j = 0; j < 8; j++) {
            mx0 = fmaxf(mx0, fmaxf(c[j][0], c[j][1]));
            mx1 = fmaxf(mx1, fmaxf(c[j][2], c[j][3]));
        }
        #pragma unroll
        for (int off = 1; off <= 2; off <<= 1) {
            mx0 = fmaxf(mx0, __shfl_xor_sync(0xffffffffu, mx0, off));
            mx1 = fmaxf(mx1, __shfl_xor_sync(0xffffffffu, mx1, off));
        }
        float mn0 = fmaxf(m0v, mx0), mn1 = fmaxf(m1v, mx1);
        float a0 = exp2f(m0v - mn0), a1 = exp2f(m1v - mn1);
        float rs0 = 0.f, rs1 = 0.f;
        uint32_t phi[8][2], plo[8][2];
        #pragma unroll
        for (int j = 0; j < 8; j++) {
            float p0 = exp2f(c[j][0] - mn0);
            float p1 = exp2f(c[j][1] - mn0);
            float p2 = exp2f(c[j][2] - mn1);
            float p3 = exp2f(c[j][3] - mn1);
            rs0 += p0 + p1; rs1 += p2 + p3;
            split2(p0, p1, phi[j][0], plo[j][0]);
            split2(p2, p3, phi[j][1], plo[j][1]);
        }
        #pragma unroll
        for (int off = 1; off <= 2; off <<= 1) {
            rs0 += __shfl_xor_sync(0xffffffffu, rs0, off);
            rs1 += __shfl_xor_sync(0xffffffffu, rs1, off);
        }
        l0v = l0v * a0 + rs0;  m0v = mn0;
        l1v = l1v * a1 + rs1;  m1v = mn1;
        #pragma unroll
        for (int j = 0; j < 16; j++) {
            o[j][0] *= a0; o[j][1] *= a0;
            o[j][2] *= a1; o[j][3] *= a1;
        }

        // Wait for V(t)
        if (t + 1 < cnt) { CP_WAIT1(); } else { CP_WAIT0(); }
        __syncthreads();

        // O += P V : 3-term
        #pragma unroll
        for (int s = 0; s < 4; s++) {
            uint32_t ap[4]  = { phi[2*s][0], phi[2*s][1], phi[2*s+1][0], phi[2*s+1][1] };
            uint32_t alo[4] = { plo[2*s][0], plo[2*s][1], plo[2*s+1][0], plo[2*s+1][1] };
            uint32_t vaddr = sb + A_VH + (16 * s + (L & 15)) * KV_ROWB + (L >> 4) * 16;
            #pragma unroll
            for (int jj = 0; jj < 16; jj += 2) {
                uint32_t bh[4], bl[4];
                ldsm_x4_t(bh, vaddr + 16 * jj);
                ldsm_x4_t(bl, vaddr + 16 * jj + KTILE);
                mma_bf16(o[jj],     ap,  bh);
                mma_bf16(o[jj],     alo, bh);
                mma_bf16(o[jj],     ap,  bl);
                mma_bf16(o[jj + 1], ap,  bh + 2);
                mma_bf16(o[jj + 1], alo, bh + 2);
                mma_bf16(o[jj + 1], ap,  bl + 2);
            }
        }

        __syncthreads();
        if (t + 1 < cnt) { prefetch_v((tile + 1) * 64); CP_COMMIT(); }
    }

    const bool full = (kt0 == 0) && (cnt == qt + 1);   // covers entire causal range
    int r0 = 16 * w + lr;
    if (full) {
        // Write normalized output directly (no merge needed)
        float inv0 = __frcp_rn(l0v), inv1 = __frcp_rn(l1v);
        #pragma unroll
        for (int jj = 0; jj < 16; jj++) {
            int cc = 8 * jj + lc;
            *(float2*)&out[((size_t)b * Tq + q0 + r0) * HSq + cc] =
                make_float2(o[jj][0] * inv0, o[jj][1] * inv0);
            *(float2*)&out[((size_t)b * Tq + q0 + r0 + 8) * HSq + cc] =
                make_float2(o[jj][2] * inv1, o[jj][3] * inv1);
        }
    } else {
        // Store unnormalized partial (O, m, l)
        const int part = (kt0 == 0) ? 0 : 1;
        const size_t pb = (((size_t)b * 32 + qt) * 2 + part) * (64 * 128);
        const size_t mb = (((size_t)b * 32 + qt) * 2 + part) * 64;
        #pragma unroll
        for (int jj = 0; jj < 16; jj++) {
            int cc = 8 * jj + lc;
            *(float2*)&g_po[pb + (size_t)r0 * 128 + cc] = make_float2(o[jj][0], o[jj][1]);
            *(float2*)&g_po[pb + (size_t)(r0 + 8) * 128 + cc] = make_float2(o[jj][2], o[jj][3]);
        }
        if ((L & 3) == 0) {
            g_pm[mb + r0] = m0v;  g_pl[mb + r0] = l0v;
            g_pm[mb + r0 + 8] = m1v;  g_pl[mb + r0 + 8] = l1v;
        }
    }
}

// ---------------------------------------------------------------------------
// Kernel 3: merge partials for qt >= 16 (two parts each). Grid (16, 8).
// ---------------------------------------------------------------------------
__global__ __launch_bounds__(256) void merge_kernel(float* __restrict__ out)
{
    const int qt = 16 + blockIdx.x;
    const int b  = blockIdx.y;
    const int tid = threadIdx.x;
    const size_t base0 = (((size_t)b * 32 + qt) * 2 + 0) * (64 * 128);
    const size_t base1 = base0 + 64 * 128;
    const size_t mb0 = (((size_t)b * 32 + qt) * 2 + 0) * 64;
    const size_t mb1 = mb0 + 64;

    #pragma unroll
    for (int i = 0; i < 8; i++) {
        int idx = tid + i * 256;        // float4 index, 2048 total
        int off = idx * 4;
        int row = off >> 7;
        int col = off & 127;
        float4 a = *(const float4*)&g_po[base0 + off];
        float4 bb = *(const float4*)&g_po[base1 + off];
        float mA = g_pm[mb0 + row], lA = g_pl[mb0 + row];
        float mB = g_pm[mb1 + row], lB = g_pl[mb1 + row];
        float m = fmaxf(mA, mB);
        float wA = exp2f(mA - m), wB = exp2f(mB - m);
        float inv = __frcp_rn(lA * wA + lB * wB);
        float4 res = make_float4((a.x * wA + bb.x * wB) * inv,
                                 (a.y * wA + bb.y * wB) * inv,
                                 (a.z * wA + bb.z * wB) * inv,
                                 (a.w * wA + bb.w * wB) * inv);
        *(float4*)&out[((size_t)b * Tq + qt * 64 + row) * HSq + col] = res;
    }
}

// ---------------------------------------------------------------------------
extern "C" void kernel_launch(void* const* d_in, const int* in_sizes, int n_in,
                              void* d_out, int out_size)
{
    const float* x  = (const float*)d_in[0];
    const float* Wq = (const float*)d_in[1];
    const float* Wk = (const float*)d_in[2];
    const float* Wv = (const float*)d_in[3];
    float* out = (float*)d_out;

    cudaFuncSetAttribute(proj_mma_kernel, cudaFuncAttributeMaxDynamicSharedMemorySize,
                         PROJ_SMEM);
    cudaFuncSetAttribute(attn_mma_kernel, cudaFuncAttributeMaxDynamicSharedMemorySize,
                         ATTN_SMEM);

    prep_x_kernel<<<BT * Dq / (256 * 8), 256>>>(x);

    dim3 wgrid(Dq / 32, NTOT / 32);
    prep_w_kernel<<<wgrid, dim3(32, 8)>>>(Wq, Wk, Wv);

    dim3 pgrid(BT / 128, 3);
    proj_mma_kernel<<<pgrid, 256, PROJ_SMEM>>>();

    dim3 agrid(Bq, 48);
    attn_mma_kernel<<<agrid, 128, ATTN_SMEM>>>(out);

    dim3 mgrid(16, Bq);
    merge_kernel<<<mgrid, 256>>>(out);
}

// round 11
// speedup vs baseline: 1.6284x; 1.0960x over previous
#include <cuda_runtime.h>
#include <cuda_bf16.h>
#include <cuda_fp16.h>
#include <math.h>
#include <cstdint>

#define Bq   8
#define Tq   2048
#define Dq   1024
#define HSq  128
#define BT   (Bq * Tq)        // 16384 rows
#define NTOT 384              // 3 * HS

// Scratch (device globals — no allocs allowed).
__device__ __align__(256) __half g_x_hi[BT * Dq];            // x split, fp16 (exact 2-term)
__device__ __align__(256) __half g_x_lo[BT * Dq];
__device__ __align__(256) __half g_wt_h[NTOT * Dq];          // W^T fp16 (Wq pre-scaled)
__device__ __align__(256) __half g_q_hi[BT * HSq];           // q exact fp16 2-term
__device__ __align__(256) __half g_q_lo[BT * HSq];
__device__ __align__(256) __half g_k[BT * HSq];              // k single fp16
__device__ __align__(256) __half g_v_hi[BT * HSq];           // v exact fp16 2-term
__device__ __align__(256) __half g_v_lo[BT * HSq];

// Split-KV partials: [b][qt][part][64][128] fp32 + per-row m,l (base-2 logits)
__device__ __align__(256) float g_po[Bq * 32 * 2 * 64 * 128];   // 16 MB
__device__ __align__(256) float g_pm[Bq * 32 * 2 * 64];
__device__ __align__(256) float g_pl[Bq * 32 * 2 * 64];

// Chunk LUT (48 chunks per batch), heavy-first (cnt descending).
__device__ const int c_qt[48]  = {15,16,17,18,19,20,21,22,23,24,25,26,27,28,29,30,31,31,
                                  14,30,13,29,12,28,11,27,10,26, 9,25, 8,24, 7,23,
                                   6,22, 5,21, 4,20, 3,19, 2,18, 1,17, 0,16};
__device__ const int c_k0[48]  = { 0, 0, 0, 0, 0, 0, 0, 0, 0, 0, 0, 0, 0, 0, 0, 0, 0,16,
                                   0,16, 0,16, 0,16, 0,16, 0,16, 0,16, 0,16, 0,16,
                                   0,16, 0,16, 0,16, 0,16, 0,16, 0,16, 0,16};
__device__ const int c_cnt[48] = {16,16,16,16,16,16,16,16,16,16,16,16,16,16,16,16,16,16,
                                  15,15,14,14,13,13,12,12,11,11,10,10, 9, 9, 8, 8,
                                   7, 7, 6, 6, 5, 5, 4, 4, 3, 3, 2, 2, 1, 1};

// ---------------------------------------------------------------------------
// Helpers
// ---------------------------------------------------------------------------
__device__ __forceinline__ void mma_f16(float* c, const uint32_t* a, const uint32_t* b) {
    asm volatile(
        "mma.sync.aligned.m16n8k16.row.col.f32.f16.f16.f32 "
        "{%0,%1,%2,%3}, {%4,%5,%6,%7}, {%8,%9}, {%0,%1,%2,%3};"
        : "+f"(c[0]), "+f"(c[1]), "+f"(c[2]), "+f"(c[3])
        : "r"(a[0]), "r"(a[1]), "r"(a[2]), "r"(a[3]), "r"(b[0]), "r"(b[1]));
}
__device__ __forceinline__ void ldsm_x4(uint32_t* r, uint32_t addr) {
    asm volatile("ldmatrix.sync.aligned.m8n8.x4.shared.b16 {%0,%1,%2,%3}, [%4];"
                 : "=r"(r[0]), "=r"(r[1]), "=r"(r[2]), "=r"(r[3]) : "r"(addr));
}
__device__ __forceinline__ void ldsm_x4_t(uint32_t* r, uint32_t addr) {
    asm volatile("ldmatrix.sync.aligned.m8n8.x4.trans.shared.b16 {%0,%1,%2,%3}, [%4];"
                 : "=r"(r[0]), "=r"(r[1]), "=r"(r[2]), "=r"(r[3]) : "r"(addr));
}
__device__ __forceinline__ uint32_t smem_u32(const void* p) {
    uint32_t a;
    asm("{ .reg .u64 t; cvta.to.shared.u64 t, %1; cvt.u32.u64 %0, t; }"
        : "=r"(a) : "l"(p));
    return a;
}
__device__ __forceinline__ void cp16(uint32_t dst, const void* src) {
    asm volatile("cp.async.cg.shared.global [%0], [%1], 16;" :: "r"(dst), "l"(src));
}
#define CP_COMMIT() asm volatile("cp.async.commit_group;" ::: "memory")
#define CP_WAIT0()  asm volatile("cp.async.wait_group 0;" ::: "memory")
#define CP_WAIT1()  asm volatile("cp.async.wait_group 1;" ::: "memory")

// fp16 hi/lo split (exact to 2^-22)
__device__ __forceinline__ void split2h(float v0, float v1, uint32_t& hi, uint32_t& lo) {
    __half2 h2 = __floats2half2_rn(v0, v1);
    float2 f = __half22float2(h2);
    __half2 l2 = __floats2half2_rn(v0 - f.x, v1 - f.y);
    hi = *(uint32_t*)&h2;
    lo = *(uint32_t*)&l2;
}
__device__ __forceinline__ uint32_t packh2(float v0, float v1) {
    __half2 h2 = __floats2half2_rn(v0, v1);
    return *(uint32_t*)&h2;
}

// ---------------------------------------------------------------------------
// Kernel 0a: split x -> fp16 hi/lo. 8 floats per thread.
// ---------------------------------------------------------------------------
__global__ __launch_bounds__(256) void prep_x_kernel(const float* __restrict__ x)
{
    size_t i = ((size_t)blockIdx.x * 256 + threadIdx.x) * 8;
    float4 a = *(const float4*)&x[i];
    float4 b = *(const float4*)&x[i + 4];
    uint32_t h0, l0, h1, l1, h2, l2, h3, l3;
    split2h(a.x, a.y, h0, l0); split2h(a.z, a.w, h1, l1);
    split2h(b.x, b.y, h2, l2); split2h(b.z, b.w, h3, l3);
    *(uint4*)&g_x_hi[i] = make_uint4(h0, h1, h2, h3);
    *(uint4*)&g_x_lo[i] = make_uint4(l0, l1, l2, l3);
}

// ---------------------------------------------------------------------------
// Kernel 0b: transpose + convert weights to fp16 (Wq scaled by 128^-0.5*log2e).
// ---------------------------------------------------------------------------
__global__ void prep_w_kernel(const float* __restrict__ Wq,
                              const float* __restrict__ Wk,
                              const float* __restrict__ Wv)
{
    __shared__ float t[32][33];
    const int k0 = blockIdx.x * 32;
    const int n0 = blockIdx.y * 32;
    const int slab = n0 >> 7;
    const float* W = (slab == 0) ? Wq : (slab == 1) ? Wk : Wv;
    const float sc = (slab == 0) ? (0.08838834764831845f * 1.4426950408889634f) : 1.0f;
    const int nn0 = n0 & 127;
    const int tx = threadIdx.x, ty = threadIdx.y;

    #pragma unroll
    for (int i = 0; i < 4; i++)
        t[ty * 4 + i][tx] = W[(size_t)(k0 + ty * 4 + i) * HSq + nn0 + tx] * sc;
    __syncthreads();
    #pragma unroll
    for (int i = 0; i < 4; i++) {
        int nr = ty * 4 + i;
        g_wt_h[(size_t)(n0 + nr) * Dq + k0 + tx] = __float2half_rn(t[tx][nr]);
    }
}

// ---------------------------------------------------------------------------
// Kernel 1: QKV projection, fp16 2-term HMMA (x split hi/lo, W single fp16).
// Grid (128 M-tiles, 3 slabs), block 256 (8 warps, 4x2). BM=128 BN=128 BK=32.
// ---------------------------------------------------------------------------
#define PS      80            // smem row pitch bytes (40 fp16)
#define P_ARR   (128 * PS)    // 10240
#define P_XH    0
#define P_XL    (1 * P_ARR)
#define P_WH    (2 * P_ARR)
#define P_BUF   (3 * P_ARR)   // 30720
#define PROJ_SMEM (2 * P_BUF) // 61440

__global__ __launch_bounds__(256, 2) void proj_mma_kernel()
{
    extern __shared__ __align__(16) char smc[];
    const uint32_t sb = smem_u32(smc);
    const int tid = threadIdx.x;
    const int w   = tid >> 5;
    const int L   = tid & 31;
    const int m0  = blockIdx.x * 128;
    const int nt  = blockIdx.y;                   // 0:q 1:k 2:v

    const __half* wh  = g_wt_h + (size_t)nt * HSq * Dq;
    const __half* xhi = g_x_hi + (size_t)m0 * Dq;
    const __half* xlo = g_x_lo + (size_t)m0 * Dq;

    const int mrow  = (w & 3) * 32;
    const int nbase = (w >> 2) * 64;

    float c[2][8][4];
    #pragma unroll
    for (int mt = 0; mt < 2; mt++)
        #pragma unroll
        for (int j = 0; j < 8; j++)
            #pragma unroll
            for (int r = 0; r < 4; r++) c[mt][j][r] = 0.f;

    auto prefetch = [&](int ch, uint32_t bb) {
        const int kb = ch * 32;
        #pragma unroll
        for (int i = 0; i < 2; i++) {
            int idx = tid + i * 256;
            int r = idx >> 2, q = idx & 3;
            uint32_t d = bb + r * PS + q * 16;
            cp16(d + P_XH, xhi + (size_t)r * Dq + kb + q * 8);
            cp16(d + P_XL, xlo + (size_t)r * Dq + kb + q * 8);
            cp16(d + P_WH, wh  + (size_t)r * Dq + kb + q * 8);
        }
    };

    prefetch(0, sb);
    CP_COMMIT();

    for (int ch = 0; ch < Dq / 32; ch++) {
        if (ch + 1 < Dq / 32) prefetch(ch + 1, sb + ((ch + 1) & 1) * P_BUF);
        CP_COMMIT();
        CP_WAIT1();
        __syncthreads();

        const uint32_t base = sb + (ch & 1) * P_BUF;

        // A fragments (x hi/lo): ldmatrix.x4
        uint32_t ah[2][2][4], al[2][2][4];
        #pragma unroll
        for (int mt = 0; mt < 2; mt++) {
            uint32_t arow = base + P_XH
                + (uint32_t)(mrow + mt * 16 + (L & 7) + ((L >> 3) & 1) * 8) * PS
                + (L >> 4) * 16;
            #pragma unroll
            for (int ks = 0; ks < 2; ks++) {
                ldsm_x4(ah[mt][ks], arow + ks * 32);
                ldsm_x4(al[mt][ks], arow + ks * 32 + (P_XL - P_XH));
            }
        }

        #pragma unroll
        for (int j = 0; j < 8; j++) {
            uint32_t brow = base + P_WH
                + (uint32_t)(nbase + 8 * j + (L & 7)) * PS + ((L >> 3) & 3) * 16;
            uint32_t bh[4];
            ldsm_x4(bh, brow);
            #pragma unroll
            for (int t = 0; t < 2; t++) {
                #pragma unroll
                for (int ks = 0; ks < 2; ks++) {
                    #pragma unroll
                    for (int mt = 0; mt < 2; mt++) {
                        mma_f16(c[mt][j], t ? al[mt][ks] : ah[mt][ks], bh + 2 * ks);
                    }
                }
            }
        }
        __syncthreads();
    }

    // Epilogue: q -> exact fp16 hi/lo; k -> single fp16; v -> exact fp16 hi/lo
    #pragma unroll
    for (int mt = 0; mt < 2; mt++) {
        int r0 = m0 + mrow + mt * 16 + (L >> 2);
        #pragma unroll
        for (int j = 0; j < 8; j++) {
            int cc = nbase + 8 * j + (L & 3) * 2;
            if (nt == 1) {
                *(uint32_t*)&g_k[(size_t)r0 * HSq + cc] = packh2(c[mt][j][0], c[mt][j][1]);
                *(uint32_t*)&g_k[(size_t)(r0 + 8) * HSq + cc] = packh2(c[mt][j][2], c[mt][j][3]);
            } else {
                __half* oh = (nt == 0) ? g_q_hi : g_v_hi;
                __half* ol = (nt == 0) ? g_q_lo : g_v_lo;
                uint32_t h, l;
                split2h(c[mt][j][0], c[mt][j][1], h, l);
                *(uint32_t*)&oh[(size_t)r0 * HSq + cc] = h;
                *(uint32_t*)&ol[(size_t)r0 * HSq + cc] = l;
                split2h(c[mt][j][2], c[mt][j][3], h, l);
                *(uint32_t*)&oh[(size_t)(r0 + 8) * HSq + cc] = h;
                *(uint32_t*)&ol[(size_t)(r0 + 8) * HSq + cc] = l;
            }
        }
    }
}

// ---------------------------------------------------------------------------
// Kernel 2: split-KV causal flash attention, fp16 asymmetric 2-term.
// S = Qhi*K + Qlo*K (K single fp16); O = P*Vhi + P*Vlo (P single fp16).
// K double-buffered, V hi/lo single-buffered. smem 69632, 2 CTAs/SM.
// Grid (8 batch, 48 chunks heavy-first). Block 128 (4 warps).
// ---------------------------------------------------------------------------
#define KV_ROWB 272                        // 128 fp16 data + 8 pad
#define KTILE   (64 * KV_ROWB)             // 17408
#define A_K0    0
#define A_K1    (1 * KTILE)
#define A_VH    (2 * KTILE)
#define A_VL    (3 * KTILE)
#define ATTN_SMEM (4 * KTILE)              // 69632

__global__ __launch_bounds__(128, 2) void attn_mma_kernel(float* __restrict__ out)
{
    extern __shared__ __align__(16) char smc[];
    const uint32_t sb = smem_u32(smc);
    const int tid = threadIdx.x;
    const int w   = tid >> 5;
    const int L   = tid & 31;
    const int b   = blockIdx.x;
    const int cid = blockIdx.y;
    const int qt  = c_qt[cid];
    const int kt0 = c_k0[cid];
    const int cnt = c_cnt[cid];
    const int q0  = qt * 64;

    const __half* qh_g = g_q_hi + (size_t)b * Tq * HSq;
    const __half* ql_g = g_q_lo + (size_t)b * Tq * HSq;
    const __half* k_g  = g_k    + (size_t)b * Tq * HSq;
    const __half* vh_g = g_v_hi + (size_t)b * Tq * HSq;
    const __half* vl_g = g_v_lo + (size_t)b * Tq * HSq;

    const int lr = L >> 2;
    const int lc = (L & 3) * 2;

    auto prefetch_k = [&](int krow, int buf) {
        uint32_t kb = sb + (buf ? A_K1 : A_K0);
        #pragma unroll
        for (int i = 0; i < 8; i++) {
            int idx = tid + i * 128;
            int r = idx >> 4, q = idx & 15;
            cp16(kb + r * KV_ROWB + q * 16, k_g + (size_t)(krow + r) * HSq + q * 8);
        }
    };
    auto prefetch_v = [&](int krow) {
        #pragma unroll
        for (int i = 0; i < 8; i++) {
            int idx = tid + i * 128;
            int r = idx >> 4, q = idx & 15;
            uint32_t d = r * KV_ROWB + q * 16;
            size_t so = (size_t)(krow + r) * HSq + q * 8;
            cp16(sb + A_VH + d, vh_g + so);
            cp16(sb + A_VL + d, vl_g + so);
        }
    };

    // Q fragments (pre-scaled by 128^-0.5*log2e, exact fp16 split)
    uint32_t qh[8][4], ql[8][4];
    #pragma unroll
    for (int s = 0; s < 8; s++)
        #pragma unroll
        for (int i = 0; i < 4; i++) {
            int rr = q0 + 16 * w + lr + 8 * (i & 1);
            int cc = 16 * s + lc + 8 * (i >> 1);
            qh[s][i] = *(const uint32_t*)&qh_g[(size_t)rr * HSq + cc];
            ql[s][i] = *(const uint32_t*)&ql_g[(size_t)rr * HSq + cc];
        }

    float o[16][4];
    #pragma unroll
    for (int j = 0; j < 16; j++)
        #pragma unroll
        for (int r = 0; r < 4; r++) o[j][r] = 0.f;
    float m0v = -1e30f, m1v = -1e30f, l0v = 0.f, l1v = 0.f;

    prefetch_k(kt0 * 64, 0); CP_COMMIT();
    prefetch_v(kt0 * 64);    CP_COMMIT();

    for (int t = 0; t < cnt; t++) {
        const int tile = kt0 + t;
        CP_WAIT1();           // K(t) complete
        __syncthreads();
        if (t + 1 < cnt) { prefetch_k((tile + 1) * 64, (t + 1) & 1); CP_COMMIT(); }

        const uint32_t kbuf = sb + ((t & 1) ? A_K1 : A_K0);

        // S = Q K^T : 2-term (Qhi, Qlo) x single-fp16 K
        float c[8][4];
        #pragma unroll
        for (int j = 0; j < 8; j++) {
            c[j][0] = c[j][1] = c[j][2] = c[j][3] = 0.f;
            uint32_t rowaddr = kbuf + (8 * j + (L & 7)) * KV_ROWB + ((L >> 3) & 3) * 16;
            #pragma unroll
            for (int sp = 0; sp < 4; sp++) {
                uint32_t bh[4];
                ldsm_x4(bh, rowaddr + 64 * sp);
                mma_f16(c[j], qh[2 * sp],     bh);
                mma_f16(c[j], ql[2 * sp],     bh);
                mma_f16(c[j], qh[2 * sp + 1], bh + 2);
                mma_f16(c[j], ql[2 * sp + 1], bh + 2);
            }
        }

        // Causal mask on diagonal tile
        if (tile == qt) {
            int r0 = 16 * w + lr, r1 = r0 + 8;
            #pragma unroll
            for (int j = 0; j < 8; j++) {
                int n0 = 8 * j + lc;
                if (n0 > r0)     c[j][0] = -1e30f;
                if (n0 + 1 > r0) c[j][1] = -1e30f;
                if (n0 > r1)     c[j][2] = -1e30f;
                if (n0 + 1 > r1) c[j][3] = -1e30f;
            }
        }

        // Online softmax (base-2); P packed to single fp16
        float mx0 = -1e30f, mx1 = -1e30f;
        #pragma unroll
        for (int j = 0; j < 8; j++) {
            mx0 = fmaxf(mx0, fmaxf(c[j][0], c[j][1]));
            mx1 = fmaxf(mx1, fmaxf(c[j][2], c[j][3]));
        }
        #pragma unroll
        for (int off = 1; off <= 2; off <<= 1) {
            mx0 = fmaxf(mx0, __shfl_xor_sync(0xffffffffu, mx0, off));
            mx1 = fmaxf(mx1, __shfl_xor_sync(0xffffffffu, mx1, off));
        }
        float mn0 = fmaxf(m0v, mx0), mn1 = fmaxf(m1v, mx1);
        float a0 = exp2f(m0v - mn0), a1 = exp2f(m1v - mn1);
        float rs0 = 0.f, rs1 = 0.f;
        uint32_t ph[8][2];
        #pragma unroll
        for (int j = 0; j < 8; j++) {
            float p0 = exp2f(c[j][0] - mn0);
            float p1 = exp2f(c[j][1] - mn0);
            float p2 = exp2f(c[j][2] - mn1);
            float p3 = exp2f(c[j][3] - mn1);
            rs0 += p0 + p1; rs1 += p2 + p3;
            ph[j][0] = packh2(p0, p1);
            ph[j][1] = packh2(p2, p3);
        }
        #pragma unroll
        for (int off = 1; off <= 2; off <<= 1) {
            rs0 += __shfl_xor_sync(0xffffffffu, rs0, off);
            rs1 += __shfl_xor_sync(0xffffffffu, rs1, off);
        }
        l0v = l0v * a0 + rs0;  m0v = mn0;
        l1v = l1v * a1 + rs1;  m1v = mn1;
        #pragma unroll
        for (int j = 0; j < 16; j++) {
            o[j][0] *= a0; o[j][1] *= a0;
            o[j][2] *= a1; o[j][3] *= a1;
        }

        // Wait for V(t)
        if (t + 1 < cnt) { CP_WAIT1(); } else { CP_WAIT0(); }
        __syncthreads();

        // O += P V : single-fp16 P x (Vhi + Vlo)
        #pragma unroll
        for (int s = 0; s < 4; s++) {
            uint32_t ap[4] = { ph[2*s][0], ph[2*s][1], ph[2*s+1][0], ph[2*s+1][1] };
            uint32_t vaddr = sb + A_VH + (16 * s + (L & 15)) * KV_ROWB + (L >> 4) * 16;
            #pragma unroll
            for (int jj = 0; jj < 16; jj += 2) {
                uint32_t bh[4], bl[4];
                ldsm_x4_t(bh, vaddr + 16 * jj);
                ldsm_x4_t(bl, vaddr + 16 * jj + (A_VL - A_VH));
                mma_f16(o[jj],     ap, bh);
                mma_f16(o[jj],     ap, bl);
                mma_f16(o[jj + 1], ap, bh + 2);
                mma_f16(o[jj + 1], ap, bl + 2);
            }
        }

        __syncthreads();
        if (t + 1 < cnt) { prefetch_v((tile + 1) * 64); CP_COMMIT(); }
    }

    const bool full = (kt0 == 0) && (cnt == qt + 1);   // covers entire causal range
    int r0 = 16 * w + lr;
    if (full) {
        float inv0 = __frcp_rn(l0v), inv1 = __frcp_rn(l1v);
        #pragma unroll
        for (int jj = 0; jj < 16; jj++) {
            int cc = 8 * jj + lc;
            *(float2*)&out[((size_t)b * Tq + q0 + r0) * HSq + cc] =
                make_float2(o[jj][0] * inv0, o[jj][1] * inv0);
            *(float2*)&out[((size_t)b * Tq + q0 + r0 + 8) * HSq + cc] =
                make_float2(o[jj][2] * inv1, o[jj][3] * inv1);
        }
    } else {
        const int part = (kt0 == 0) ? 0 : 1;
        const size_t pb = (((size_t)b * 32 + qt) * 2 + part) * (64 * 128);
        const size_t mb = (((size_t)b * 32 + qt) * 2 + part) * 64;
        #pragma unroll
        for (int jj = 0; jj < 16; jj++) {
            int cc = 8 * jj + lc;
            *(float2*)&g_po[pb + (size_t)r0 * 128 + cc] = make_float2(o[jj][0], o[jj][1]);
            *(float2*)&g_po[pb + (size_t)(r0 + 8) * 128 + cc] = make_float2(o[jj][2], o[jj][3]);
        }
        if ((L & 3) == 0) {
            g_pm[mb + r0] = m0v;  g_pl[mb + r0] = l0v;
            g_pm[mb + r0 + 8] = m1v;  g_pl[mb + r0 + 8] = l1v;
        }
    }
}

// ---------------------------------------------------------------------------
// Kernel 3: merge partials for qt >= 16 (two parts each). Grid (16, 8).
// ---------------------------------------------------------------------------
__global__ __launch_bounds__(256) void merge_kernel(float* __restrict__ out)
{
    const int qt = 16 + blockIdx.x;
    const int b  = blockIdx.y;
    const int tid = threadIdx.x;
    const size_t base0 = (((size_t)b * 32 + qt) * 2 + 0) * (64 * 128);
    const size_t base1 = base0 + 64 * 128;
    const size_t mb0 = (((size_t)b * 32 + qt) * 2 + 0) * 64;
    const size_t mb1 = mb0 + 64;

    #pragma unroll
    for (int i = 0; i < 8; i++) {
        int idx = tid + i * 256;        // float4 index, 2048 total
        int off = idx * 4;
        int row = off >> 7;
        int col = off & 127;
        float4 a = *(const float4*)&g_po[base0 + off];
        float4 bb = *(const float4*)&g_po[base1 + off];
        float mA = g_pm[mb0 + row], lA = g_pl[mb0 + row];
        float mB = g_pm[mb1 + row], lB = g_pl[mb1 + row];
        float m = fmaxf(mA, mB);
        float wA = exp2f(mA - m), wB = exp2f(mB - m);
        float inv = __frcp_rn(lA * wA + lB * wB);
        float4 res = make_float4((a.x * wA + bb.x * wB) * inv,
                                 (a.y * wA + bb.y * wB) * inv,
                                 (a.z * wA + bb.z * wB) * inv,
                                 (a.w * wA + bb.w * wB) * inv);
        *(float4*)&out[((size_t)b * Tq + qt * 64 + row) * HSq + col] = res;
    }
}

// ---------------------------------------------------------------------------
extern "C" void kernel_launch(void* const* d_in, const int* in_sizes, int n_in,
                              void* d_out, int out_size)
{
    const float* x  = (const float*)d_in[0];
    const float* Wq = (const float*)d_in[1];
    const float* Wk = (const float*)d_in[2];
    const float* Wv = (const float*)d_in[3];
    float* out = (float*)d_out;

    cudaFuncSetAttribute(proj_mma_kernel, cudaFuncAttributeMaxDynamicSharedMemorySize,
                         PROJ_SMEM);
    cudaFuncSetAttribute(attn_mma_kernel, cudaFuncAttributeMaxDynamicSharedMemorySize,
                         ATTN_SMEM);

    prep_x_kernel<<<BT * Dq / (256 * 8), 256>>>(x);

    dim3 wgrid(Dq / 32, NTOT / 32);
    prep_w_kernel<<<wgrid, dim3(32, 8)>>>(Wq, Wk, Wv);

    dim3 pgrid(BT / 128, 3);
    proj_mma_kernel<<<pgrid, 256, PROJ_SMEM>>>();

    dim3 agrid(Bq, 48);
    attn_mma_kernel<<<agrid, 128, ATTN_SMEM>>>(out);

    dim3 mgrid(16, Bq);
    merge_kernel<<<mgrid, 256>>>(out);
}

// round 13
// speedup vs baseline: 2.2054x; 1.3543x over previous
#include <cuda_runtime.h>
#include <cuda_bf16.h>
#include <cuda_fp16.h>
#include <math.h>
#include <cstdint>

#define Bq   8
#define Tq   2048
#define Dq   1024
#define HSq  128
#define BT   (Bq * Tq)        // 16384 rows
#define NTOT 384              // 3 * HS

// Scratch (device globals — no allocs allowed).
__device__ __align__(256) __half g_x_h[BT * Dq];             // x single fp16
__device__ __align__(256) __half g_wt_h[NTOT * Dq];          // W^T fp16 (Wq pre-scaled)
__device__ __align__(256) __half g_q_hi[BT * HSq];           // q exact fp16 2-term
__device__ __align__(256) __half g_q_lo[BT * HSq];
__device__ __align__(256) __half g_k[BT * HSq];              // k single fp16
__device__ __align__(256) __half g_v_hi[BT * HSq];           // v exact fp16 2-term
__device__ __align__(256) __half g_v_lo[BT * HSq];

// Split-KV partials: [b][qt][part][64][128] fp32 + per-row m,l (base-2 logits)
__device__ __align__(256) float g_po[Bq * 32 * 2 * 64 * 128];   // 16 MB
__device__ __align__(256) float g_pm[Bq * 32 * 2 * 64];
__device__ __align__(256) float g_pl[Bq * 32 * 2 * 64];

// Chunk LUT (48 chunks per batch), heavy-first (cnt descending).
__device__ const int c_qt[48]  = {15,16,17,18,19,20,21,22,23,24,25,26,27,28,29,30,31,31,
                                  14,30,13,29,12,28,11,27,10,26, 9,25, 8,24, 7,23,
                                   6,22, 5,21, 4,20, 3,19, 2,18, 1,17, 0,16};
__device__ const int c_k0[48]  = { 0, 0, 0, 0, 0, 0, 0, 0, 0, 0, 0, 0, 0, 0, 0, 0, 0,16,
                                   0,16, 0,16, 0,16, 0,16, 0,16, 0,16, 0,16, 0,16,
                                   0,16, 0,16, 0,16, 0,16, 0,16, 0,16, 0,16};
__device__ const int c_cnt[48] = {16,16,16,16,16,16,16,16,16,16,16,16,16,16,16,16,16,16,
                                  15,15,14,14,13,13,12,12,11,11,10,10, 9, 9, 8, 8,
                                   7, 7, 6, 6, 5, 5, 4, 4, 3, 3, 2, 2, 1, 1};

// ---------------------------------------------------------------------------
// Helpers
// ---------------------------------------------------------------------------
__device__ __forceinline__ void mma_f16(float* c, const uint32_t* a, const uint32_t* b) {
    asm volatile(
        "mma.sync.aligned.m16n8k16.row.col.f32.f16.f16.f32 "
        "{%0,%1,%2,%3}, {%4,%5,%6,%7}, {%8,%9}, {%0,%1,%2,%3};"
        : "+f"(c[0]), "+f"(c[1]), "+f"(c[2]), "+f"(c[3])
        : "r"(a[0]), "r"(a[1]), "r"(a[2]), "r"(a[3]), "r"(b[0]), "r"(b[1]));
}
__device__ __forceinline__ void ldsm_x4(uint32_t* r, uint32_t addr) {
    asm volatile("ldmatrix.sync.aligned.m8n8.x4.shared.b16 {%0,%1,%2,%3}, [%4];"
                 : "=r"(r[0]), "=r"(r[1]), "=r"(r[2]), "=r"(r[3]) : "r"(addr));
}
__device__ __forceinline__ void ldsm_x4_t(uint32_t* r, uint32_t addr) {
    asm volatile("ldmatrix.sync.aligned.m8n8.x4.trans.shared.b16 {%0,%1,%2,%3}, [%4];"
                 : "=r"(r[0]), "=r"(r[1]), "=r"(r[2]), "=r"(r[3]) : "r"(addr));
}
__device__ __forceinline__ uint32_t smem_u32(const void* p) {
    uint32_t a;
    asm("{ .reg .u64 t; cvta.to.shared.u64 t, %1; cvt.u32.u64 %0, t; }"
        : "=r"(a) : "l"(p));
    return a;
}
__device__ __forceinline__ void cp16(uint32_t dst, const void* src) {
    asm volatile("cp.async.cg.shared.global [%0], [%1], 16;" :: "r"(dst), "l"(src));
}
#define CP_COMMIT() asm volatile("cp.async.commit_group;" ::: "memory")
#define CP_WAIT0()  asm volatile("cp.async.wait_group 0;" ::: "memory")
#define CP_WAIT1()  asm volatile("cp.async.wait_group 1;" ::: "memory")

// fp16 hi/lo split (exact to 2^-22)
__device__ __forceinline__ void split2h(float v0, float v1, uint32_t& hi, uint32_t& lo) {
    __half2 h2 = __floats2half2_rn(v0, v1);
    float2 f = __half22float2(h2);
    __half2 l2 = __floats2half2_rn(v0 - f.x, v1 - f.y);
    hi = *(uint32_t*)&h2;
    lo = *(uint32_t*)&l2;
}
__device__ __forceinline__ uint32_t packh2(float v0, float v1) {
    __half2 h2 = __floats2half2_rn(v0, v1);
    return *(uint32_t*)&h2;
}

// ---------------------------------------------------------------------------
// Kernel 0a: convert x -> single fp16. 8 floats per thread.
// ---------------------------------------------------------------------------
__global__ __launch_bounds__(256) void prep_x_kernel(const float* __restrict__ x)
{
    size_t i = ((size_t)blockIdx.x * 256 + threadIdx.x) * 8;
    float4 a = *(const float4*)&x[i];
    float4 b = *(const float4*)&x[i + 4];
    *(uint4*)&g_x_h[i] = make_uint4(packh2(a.x, a.y), packh2(a.z, a.w),
                                    packh2(b.x, b.y), packh2(b.z, b.w));
}

// ---------------------------------------------------------------------------
// Kernel 0b: transpose + convert weights to fp16 (Wq scaled by 128^-0.5*log2e).
// ---------------------------------------------------------------------------
__global__ void prep_w_kernel(const float* __restrict__ Wq,
                              const float* __restrict__ Wk,
                              const float* __restrict__ Wv)
{
    __shared__ float t[32][33];
    const int k0 = blockIdx.x * 32;
    const int n0 = blockIdx.y * 32;
    const int slab = n0 >> 7;
    const float* W = (slab == 0) ? Wq : (slab == 1) ? Wk : Wv;
    const float sc = (slab == 0) ? (0.08838834764831845f * 1.4426950408889634f) : 1.0f;
    const int nn0 = n0 & 127;
    const int tx = threadIdx.x, ty = threadIdx.y;

    #pragma unroll
    for (int i = 0; i < 4; i++)
        t[ty * 4 + i][tx] = W[(size_t)(k0 + ty * 4 + i) * HSq + nn0 + tx] * sc;
    __syncthreads();
    #pragma unroll
    for (int i = 0; i < 4; i++) {
        int nr = ty * 4 + i;
        g_wt_h[(size_t)(n0 + nr) * Dq + k0 + tx] = __float2half_rn(t[tx][nr]);
    }
}

// ---------------------------------------------------------------------------
// Kernel 1: QKV projection, single-fp16 HMMA (1-term). BK=64 (16 chunks).
// Grid (128 M-tiles, 3 slabs), block 256 (8 warps, 4x2). BM=128 BN=128.
// A: 4 ldsm.x4 per mt (k 0-15,16-31,32-47,48-63 at +0,+32,+64,+96 bytes).
// B: 2 ldsm.x4 per n-tile (each covers 32 k: frags [0:2]=k0-15, [2:4]=k16-31).
// ---------------------------------------------------------------------------
#define PS      144           // smem row pitch bytes (64 fp16 data + 8 pad)
#define P_ARR   (128 * PS)    // 18432
#define P_XH    0
#define P_WH    (1 * P_ARR)
#define P_BUF   (2 * P_ARR)   // 36864
#define PROJ_SMEM (2 * P_BUF) // 73728

__global__ __launch_bounds__(256, 2) void proj_mma_kernel()
{
    extern __shared__ __align__(16) char smc[];
    const uint32_t sb = smem_u32(smc);
    const int tid = threadIdx.x;
    const int w   = tid >> 5;
    const int L   = tid & 31;
    const int m0  = blockIdx.x * 128;
    const int nt  = blockIdx.y;                   // 0:q 1:k 2:v

    const __half* wh = g_wt_h + (size_t)nt * HSq * Dq;
    const __half* xh = g_x_h + (size_t)m0 * Dq;

    const int mrow  = (w & 3) * 32;
    const int nbase = (w >> 2) * 64;

    float c[2][8][4];
    #pragma unroll
    for (int mt = 0; mt < 2; mt++)
        #pragma unroll
        for (int j = 0; j < 8; j++)
            #pragma unroll
            for (int r = 0; r < 4; r++) c[mt][j][r] = 0.f;

    auto prefetch = [&](int ch, uint32_t bb) {
        const int kb = ch * 64;
        #pragma unroll
        for (int i = 0; i < 4; i++) {
            int idx = tid + i * 256;
            int r = idx >> 3, q = idx & 7;        // 8 x 16B = 128 bytes/row
            uint32_t d = bb + r * PS + q * 16;
            cp16(d + P_XH, xh + (size_t)r * Dq + kb + q * 8);
            cp16(d + P_WH, wh + (size_t)r * Dq + kb + q * 8);
        }
    };

    prefetch(0, sb);
    CP_COMMIT();

    for (int ch = 0; ch < Dq / 64; ch++) {
        if (ch + 1 < Dq / 64) prefetch(ch + 1, sb + ((ch + 1) & 1) * P_BUF);
        CP_COMMIT();
        CP_WAIT1();
        __syncthreads();

        const uint32_t base = sb + (ch & 1) * P_BUF;

        // A fragments: 2 mt x 4 k-steps, each ldsm.x4 = one 16x16 A fragment
        uint32_t ah[2][4][4];
        #pragma unroll
        for (int mt = 0; mt < 2; mt++) {
            uint32_t arow = base + P_XH
                + (uint32_t)(mrow + mt * 16 + (L & 7) + ((L >> 3) & 1) * 8) * PS
                + (L >> 4) * 16;
            #pragma unroll
            for (int ks = 0; ks < 4; ks++)
                ldsm_x4(ah[mt][ks], arow + ks * 32);
        }

        #pragma unroll
        for (int j = 0; j < 8; j++) {
            uint32_t brow = base + P_WH
                + (uint32_t)(nbase + 8 * j + (L & 7)) * PS + ((L >> 3) & 3) * 16;
            uint32_t bh[4], bh2[4];
            ldsm_x4(bh, brow);          // k 0-31  (frags [0:2], [2:4])
            ldsm_x4(bh2, brow + 64);    // k 32-63
            #pragma unroll
            for (int mt = 0; mt < 2; mt++) {
                mma_f16(c[mt][j], ah[mt][0], bh);
                mma_f16(c[mt][j], ah[mt][1], bh + 2);
                mma_f16(c[mt][j], ah[mt][2], bh2);
                mma_f16(c[mt][j], ah[mt][3], bh2 + 2);
            }
        }
        __syncthreads();
    }

    // Epilogue: q -> exact fp16 hi/lo; k -> single fp16; v -> exact fp16 hi/lo
    #pragma unroll
    for (int mt = 0; mt < 2; mt++) {
        int r0 = m0 + mrow + mt * 16 + (L >> 2);
        #pragma unroll
        for (int j = 0; j < 8; j++) {
            int cc = nbase + 8 * j + (L & 3) * 2;
            if (nt == 1) {
                *(uint32_t*)&g_k[(size_t)r0 * HSq + cc] = packh2(c[mt][j][0], c[mt][j][1]);
                *(uint32_t*)&g_k[(size_t)(r0 + 8) * HSq + cc] = packh2(c[mt][j][2], c[mt][j][3]);
            } else {
                __half* oh = (nt == 0) ? g_q_hi : g_v_hi;
                __half* ol = (nt == 0) ? g_q_lo : g_v_lo;
                uint32_t h, l;
                split2h(c[mt][j][0], c[mt][j][1], h, l);
                *(uint32_t*)&oh[(size_t)r0 * HSq + cc] = h;
                *(uint32_t*)&ol[(size_t)r0 * HSq + cc] = l;
                split2h(c[mt][j][2], c[mt][j][3], h, l);
                *(uint32_t*)&oh[(size_t)(r0 + 8) * HSq + cc] = h;
                *(uint32_t*)&ol[(size_t)(r0 + 8) * HSq + cc] = l;
            }
        }
    }
}

// ---------------------------------------------------------------------------
// Kernel 2: split-KV causal flash attention, fp16 asymmetric 2-term.
// S = Qhi*K + Qlo*K (K single fp16); O = P*Vhi + P*Vlo (P single fp16).
// K double-buffered, V hi/lo single-buffered. smem 69632, 2 CTAs/SM.
// Grid (8 batch, 48 chunks heavy-first). Block 128 (4 warps).
// ---------------------------------------------------------------------------
#define KV_ROWB 272                        // 128 fp16 data + 8 pad
#define KTILE   (64 * KV_ROWB)             // 17408
#define A_K0    0
#define A_K1    (1 * KTILE)
#define A_VH    (2 * KTILE)
#define A_VL    (3 * KTILE)
#define ATTN_SMEM (4 * KTILE)              // 69632

__global__ __launch_bounds__(128, 2) void attn_mma_kernel(float* __restrict__ out)
{
    extern __shared__ __align__(16) char smc[];
    const uint32_t sb = smem_u32(smc);
    const int tid = threadIdx.x;
    const int w   = tid >> 5;
    const int L   = tid & 31;
    const int b   = blockIdx.x;
    const int cid = blockIdx.y;
    const int qt  = c_qt[cid];
    const int kt0 = c_k0[cid];
    const int cnt = c_cnt[cid];
    const int q0  = qt * 64;

    const __half* qh_g = g_q_hi + (size_t)b * Tq * HSq;
    const __half* ql_g = g_q_lo + (size_t)b * Tq * HSq;
    const __half* k_g  = g_k    + (size_t)b * Tq * HSq;
    const __half* vh_g = g_v_hi + (size_t)b * Tq * HSq;
    const __half* vl_g = g_v_lo + (size_t)b * Tq * HSq;

    const int lr = L >> 2;
    const int lc = (L & 3) * 2;

    auto prefetch_k = [&](int krow, int buf) {
        uint32_t kb = sb + (buf ? A_K1 : A_K0);
        #pragma unroll
        for (int i = 0; i < 8; i++) {
            int idx = tid + i * 128;
            int r = idx >> 4, q = idx & 15;
            cp16(kb + r * KV_ROWB + q * 16, k_g + (size_t)(krow + r) * HSq + q * 8);
        }
    };
    auto prefetch_v = [&](int krow) {
        #pragma unroll
        for (int i = 0; i < 8; i++) {
            int idx = tid + i * 128;
            int r = idx >> 4, q = idx & 15;
            uint32_t d = r * KV_ROWB + q * 16;
            size_t so = (size_t)(krow + r) * HSq + q * 8;
            cp16(sb + A_VH + d, vh_g + so);
            cp16(sb + A_VL + d, vl_g + so);
        }
    };

    // Q fragments (pre-scaled by 128^-0.5*log2e, exact fp16 split)
    uint32_t qh[8][4], ql[8][4];
    #pragma unroll
    for (int s = 0; s < 8; s++)
        #pragma unroll
        for (int i = 0; i < 4; i++) {
            int rr = q0 + 16 * w + lr + 8 * (i & 1);
            int cc = 16 * s + lc + 8 * (i >> 1);
            qh[s][i] = *(const uint32_t*)&qh_g[(size_t)rr * HSq + cc];
            ql[s][i] = *(const uint32_t*)&ql_g[(size_t)rr * HSq + cc];
        }

    float o[16][4];
    #pragma unroll
    for (int j = 0; j < 16; j++)
        #pragma unroll
        for (int r = 0; r < 4; r++) o[j][r] = 0.f;
    float m0v = -1e30f, m1v = -1e30f, l0v = 0.f, l1v = 0.f;

    prefetch_k(kt0 * 64, 0); CP_COMMIT();
    prefetch_v(kt0 * 64);    CP_COMMIT();

    for (int t = 0; t < cnt; t++) {
        const int tile = kt0 + t;
        CP_WAIT1();           // K(t) complete
        __syncthreads();
        if (t + 1 < cnt) { prefetch_k((tile + 1) * 64, (t + 1) & 1); CP_COMMIT(); }

        const uint32_t kbuf = sb + ((t & 1) ? A_K1 : A_K0);

        // S = Q K^T : 2-term (Qhi, Qlo) x single-fp16 K
        float c[8][4];
        #pragma unroll
        for (int j = 0; j < 8; j++) {
            c[j][0] = c[j][1] = c[j][2] = c[j][3] = 0.f;
            uint32_t rowaddr = kbuf + (8 * j + (L & 7)) * KV_ROWB + ((L >> 3) & 3) * 16;
            #pragma unroll
            for (int sp = 0; sp < 4; sp++) {
                uint32_t bh[4];
                ldsm_x4(bh, rowaddr + 64 * sp);
                mma_f16(c[j], qh[2 * sp],     bh);
                mma_f16(c[j], ql[2 * sp],     bh);
                mma_f16(c[j], qh[2 * sp + 1], bh + 2);
                mma_f16(c[j], ql[2 * sp + 1], bh + 2);
            }
        }

        // Causal mask on diagonal tile
        if (tile == qt) {
            int r0 = 16 * w + lr, r1 = r0 + 8;
            #pragma unroll
            for (int j = 0; j < 8; j++) {
                int n0 = 8 * j + lc;
                if (n0 > r0)     c[j][0] = -1e30f;
                if (n0 + 1 > r0) c[j][1] = -1e30f;
                if (n0 > r1)     c[j][2] = -1e30f;
                if (n0 + 1 > r1) c[j][3] = -1e30f;
            }
        }

        // Online softmax (base-2); P packed to single fp16
        float mx0 = -1e30f, mx1 = -1e30f;
        #pragma unroll
        for (int j = 0; j < 8; j++) {
            mx0 = fmaxf(mx0, fmaxf(c[j][0], c[j][1]));
            mx1 = fmaxf(mx1, fmaxf(c[j][2], c[j][3]));
        }
        #pragma unroll
        for (int off = 1; off <= 2; off <<= 1) {
            mx0 = fmaxf(mx0, __shfl_xor_sync(0xffffffffu, mx0, off));
            mx1 = fmaxf(mx1, __shfl_xor_sync(0xffffffffu, mx1, off));
        }
        float mn0 = fmaxf(m0v, mx0), mn1 = fmaxf(m1v, mx1);
        float a0 = exp2f(m0v - mn0), a1 = exp2f(m1v - mn1);
        float rs0 = 0.f, rs1 = 0.f;
        uint32_t ph[8][2];
        #pragma unroll
        for (int j = 0; j < 8; j++) {
            float p0 = exp2f(c[j][0] - mn0);
            float p1 = exp2f(c[j][1] - mn0);
            float p2 = exp2f(c[j][2] - mn1);
            float p3 = exp2f(c[j][3] - mn1);
            rs0 += p0 + p1; rs1 += p2 + p3;
            ph[j][0] = packh2(p0, p1);
            ph[j][1] = packh2(p2, p3);
        }
        #pragma unroll
        for (int off = 1; off <= 2; off <<= 1) {
            rs0 += __shfl_xor_sync(0xffffffffu, rs0, off);
            rs1 += __shfl_xor_sync(0xffffffffu, rs1, off);
        }
        l0v = l0v * a0 + rs0;  m0v = mn0;
        l1v = l1v * a1 + rs1;  m1v = mn1;
        #pragma unroll
        for (int j = 0; j < 16; j++) {
            o[j][0] *= a0; o[j][1] *= a0;
            o[j][2] *= a1; o[j][3] *= a1;
        }

        // Wait for V(t)
        if (t + 1 < cnt) { CP_WAIT1(); } else { CP_WAIT0(); }
        __syncthreads();

        // O += P V : single-fp16 P x (Vhi + Vlo)
        #pragma unroll
        for (int s = 0; s < 4; s++) {
            uint32_t ap[4] = { ph[2*s][0], ph[2*s][1], ph[2*s+1][0], ph[2*s+1][1] };
            uint32_t vaddr = sb + A_VH + (16 * s + (L & 15)) * KV_ROWB + (L >> 4) * 16;
            #pragma unroll
            for (int jj = 0; jj < 16; jj += 2) {
                uint32_t bh[4], bl[4];
                ldsm_x4_t(bh, vaddr + 16 * jj);
                ldsm_x4_t(bl, vaddr + 16 * jj + (A_VL - A_VH));
                mma_f16(o[jj],     ap, bh);
                mma_f16(o[jj],     ap, bl);
                mma_f16(o[jj + 1], ap, bh + 2);
                mma_f16(o[jj + 1], ap, bl + 2);
            }
        }

        __syncthreads();
        if (t + 1 < cnt) { prefetch_v((tile + 1) * 64); CP_COMMIT(); }
    }

    const bool full = (kt0 == 0) && (cnt == qt + 1);   // covers entire causal range
    int r0 = 16 * w + lr;
    if (full) {
        float inv0 = __frcp_rn(l0v), inv1 = __frcp_rn(l1v);
        #pragma unroll
        for (int jj = 0; jj < 16; jj++) {
            int cc = 8 * jj + lc;
            *(float2*)&out[((size_t)b * Tq + q0 + r0) * HSq + cc] =
                make_float2(o[jj][0] * inv0, o[jj][1] * inv0);
            *(float2*)&out[((size_t)b * Tq + q0 + r0 + 8) * HSq + cc] =
                make_float2(o[jj][2] * inv1, o[jj][3] * inv1);
        }
    } else {
        const int part = (kt0 == 0) ? 0 : 1;
        const size_t pb = (((size_t)b * 32 + qt) * 2 + part) * (64 * 128);
        const size_t mb = (((size_t)b * 32 + qt) * 2 + part) * 64;
        #pragma unroll
        for (int jj = 0; jj < 16; jj++) {
            int cc = 8 * jj + lc;
            *(float2*)&g_po[pb + (size_t)r0 * 128 + cc] = make_float2(o[jj][0], o[jj][1]);
            *(float2*)&g_po[pb + (size_t)(r0 + 8) * 128 + cc] = make_float2(o[jj][2], o[jj][3]);
        }
        if ((L & 3) == 0) {
            g_pm[mb + r0] = m0v;  g_pl[mb + r0] = l0v;
            g_pm[mb + r0 + 8] = m1v;  g_pl[mb + r0 + 8] = l1v;
        }
    }
}

// ---------------------------------------------------------------------------
// Kernel 3: merge partials for qt >= 16 (two parts each). Grid (16, 8).
// ---------------------------------------------------------------------------
__global__ __launch_bounds__(256) void merge_kernel(float* __restrict__ out)
{
    const int qt = 16 + blockIdx.x;
    const int b  = blockIdx.y;
    const int tid = threadIdx.x;
    const size_t base0 = (((size_t)b * 32 + qt) * 2 + 0) * (64 * 128);
    const size_t base1 = base0 + 64 * 128;
    const size_t mb0 = (((size_t)b * 32 + qt) * 2 + 0) * 64;
    const size_t mb1 = mb0 + 64;

    #pragma unroll
    for (int i = 0; i < 8; i++) {
        int idx = tid + i * 256;        // float4 index, 2048 total
        int off = idx * 4;
        int row = off >> 7;
        int col = off & 127;
        float4 a = *(const float4*)&g_po[base0 + off];
        float4 bb = *(const float4*)&g_po[base1 + off];
        float mA = g_pm[mb0 + row], lA = g_pl[mb0 + row];
        float mB = g_pm[mb1 + row], lB = g_pl[mb1 + row];
        float m = fmaxf(mA, mB);
        float wA = exp2f(mA - m), wB = exp2f(mB - m);
        float inv = __frcp_rn(lA * wA + lB * wB);
        float4 res = make_float4((a.x * wA + bb.x * wB) * inv,
                                 (a.y * wA + bb.y * wB) * inv,
                                 (a.z * wA + bb.z * wB) * inv,
                                 (a.w * wA + bb.w * wB) * inv);
        *(float4*)&out[((size_t)b * Tq + qt * 64 + row) * HSq + col] = res;
    }
}

// ---------------------------------------------------------------------------
extern "C" void kernel_launch(void* const* d_in, const int* in_sizes, int n_in,
                              void* d_out, int out_size)
{
    const float* x  = (const float*)d_in[0];
    const float* Wq = (const float*)d_in[1];
    const float* Wk = (const float*)d_in[2];
    const float* Wv = (const float*)d_in[3];
    float* out = (float*)d_out;

    cudaFuncSetAttribute(proj_mma_kernel, cudaFuncAttributeMaxDynamicSharedMemorySize,
                         PROJ_SMEM);
    cudaFuncSetAttribute(attn_mma_kernel, cudaFuncAttributeMaxDynamicSharedMemorySize,
                         ATTN_SMEM);

    prep_x_kernel<<<BT * Dq / (256 * 8), 256>>>(x);

    dim3 wgrid(Dq / 32, NTOT / 32);
    prep_w_kernel<<<wgrid, dim3(32, 8)>>>(Wq, Wk, Wv);

    dim3 pgrid(BT / 128, 3);
    proj_mma_kernel<<<pgrid, 256, PROJ_SMEM>>>();

    dim3 agrid(Bq, 48);
    attn_mma_kernel<<<agrid, 128, ATTN_SMEM>>>(out);

    dim3 mgrid(16, Bq);
    merge_kernel<<<mgrid, 256>>>(out);
}

// round 14
// speedup vs baseline: 2.4828x; 1.1258x over previous
#include <cuda_runtime.h>
#include <cuda_bf16.h>
#include <cuda_fp16.h>
#include <math.h>
#include <cstdint>

#define Bq   8
#define Tq   2048
#define Dq   1024
#define HSq  128
#define BT   (Bq * Tq)        // 16384 rows
#define NTOT 384              // 3 * HS

// Scratch (device globals — no allocs allowed).
__device__ __align__(256) __half g_x_h[BT * Dq];             // x single fp16
__device__ __align__(256) __half g_wt_h[NTOT * Dq];          // W^T fp16 (Wq pre-scaled)
__device__ __align__(256) __half g_q_hi[BT * HSq];           // q exact fp16 2-term
__device__ __align__(256) __half g_q_lo[BT * HSq];
__device__ __align__(256) __half g_k[BT * HSq];              // k single fp16
__device__ __align__(256) __half g_v[BT * HSq];              // v single fp16

// Split-KV partials: [b][qt][part][64][128] fp32 + per-row m,l (base-2 logits)
__device__ __align__(256) float g_po[Bq * 32 * 2 * 64 * 128];   // 16 MB
__device__ __align__(256) float g_pm[Bq * 32 * 2 * 64];
__device__ __align__(256) float g_pl[Bq * 32 * 2 * 64];

// Chunk LUT (48 chunks per batch), heavy-first (cnt descending).
__device__ const int c_qt[48]  = {15,16,17,18,19,20,21,22,23,24,25,26,27,28,29,30,31,31,
                                  14,30,13,29,12,28,11,27,10,26, 9,25, 8,24, 7,23,
                                   6,22, 5,21, 4,20, 3,19, 2,18, 1,17, 0,16};
__device__ const int c_k0[48]  = { 0, 0, 0, 0, 0, 0, 0, 0, 0, 0, 0, 0, 0, 0, 0, 0, 0,16,
                                   0,16, 0,16, 0,16, 0,16, 0,16, 0,16, 0,16, 0,16,
                                   0,16, 0,16, 0,16, 0,16, 0,16, 0,16, 0,16};
__device__ const int c_cnt[48] = {16,16,16,16,16,16,16,16,16,16,16,16,16,16,16,16,16,16,
                                  15,15,14,14,13,13,12,12,11,11,10,10, 9, 9, 8, 8,
                                   7, 7, 6, 6, 5, 5, 4, 4, 3, 3, 2, 2, 1, 1};

// ---------------------------------------------------------------------------
// Helpers
// ---------------------------------------------------------------------------
__device__ __forceinline__ void mma_f16(float* c, const uint32_t* a, const uint32_t* b) {
    asm volatile(
        "mma.sync.aligned.m16n8k16.row.col.f32.f16.f16.f32 "
        "{%0,%1,%2,%3}, {%4,%5,%6,%7}, {%8,%9}, {%0,%1,%2,%3};"
        : "+f"(c[0]), "+f"(c[1]), "+f"(c[2]), "+f"(c[3])
        : "r"(a[0]), "r"(a[1]), "r"(a[2]), "r"(a[3]), "r"(b[0]), "r"(b[1]));
}
__device__ __forceinline__ void ldsm_x4(uint32_t* r, uint32_t addr) {
    asm volatile("ldmatrix.sync.aligned.m8n8.x4.shared.b16 {%0,%1,%2,%3}, [%4];"
                 : "=r"(r[0]), "=r"(r[1]), "=r"(r[2]), "=r"(r[3]) : "r"(addr));
}
__device__ __forceinline__ void ldsm_x4_t(uint32_t* r, uint32_t addr) {
    asm volatile("ldmatrix.sync.aligned.m8n8.x4.trans.shared.b16 {%0,%1,%2,%3}, [%4];"
                 : "=r"(r[0]), "=r"(r[1]), "=r"(r[2]), "=r"(r[3]) : "r"(addr));
}
__device__ __forceinline__ uint32_t smem_u32(const void* p) {
    uint32_t a;
    asm("{ .reg .u64 t; cvta.to.shared.u64 t, %1; cvt.u32.u64 %0, t; }"
        : "=r"(a) : "l"(p));
    return a;
}
__device__ __forceinline__ void cp16(uint32_t dst, const void* src) {
    asm volatile("cp.async.cg.shared.global [%0], [%1], 16;" :: "r"(dst), "l"(src));
}
#define CP_COMMIT() asm volatile("cp.async.commit_group;" ::: "memory")
#define CP_WAIT0()  asm volatile("cp.async.wait_group 0;" ::: "memory")
#define CP_WAIT1()  asm volatile("cp.async.wait_group 1;" ::: "memory")

// fp16 hi/lo split (exact to 2^-22)
__device__ __forceinline__ void split2h(float v0, float v1, uint32_t& hi, uint32_t& lo) {
    __half2 h2 = __floats2half2_rn(v0, v1);
    float2 f = __half22float2(h2);
    __half2 l2 = __floats2half2_rn(v0 - f.x, v1 - f.y);
    hi = *(uint32_t*)&h2;
    lo = *(uint32_t*)&l2;
}
__device__ __forceinline__ uint32_t packh2(float v0, float v1) {
    __half2 h2 = __floats2half2_rn(v0, v1);
    return *(uint32_t*)&h2;
}

// ---------------------------------------------------------------------------
// Kernel 0a: convert x -> single fp16. 8 floats per thread.
// ---------------------------------------------------------------------------
__global__ __launch_bounds__(256) void prep_x_kernel(const float* __restrict__ x)
{
    size_t i = ((size_t)blockIdx.x * 256 + threadIdx.x) * 8;
    float4 a = *(const float4*)&x[i];
    float4 b = *(const float4*)&x[i + 4];
    *(uint4*)&g_x_h[i] = make_uint4(packh2(a.x, a.y), packh2(a.z, a.w),
                                    packh2(b.x, b.y), packh2(b.z, b.w));
}

// ---------------------------------------------------------------------------
// Kernel 0b: transpose + convert weights to fp16 (Wq scaled by 128^-0.5*log2e).
// ---------------------------------------------------------------------------
__global__ void prep_w_kernel(const float* __restrict__ Wq,
                              const float* __restrict__ Wk,
                              const float* __restrict__ Wv)
{
    __shared__ float t[32][33];
    const int k0 = blockIdx.x * 32;
    const int n0 = blockIdx.y * 32;
    const int slab = n0 >> 7;
    const float* W = (slab == 0) ? Wq : (slab == 1) ? Wk : Wv;
    const float sc = (slab == 0) ? (0.08838834764831845f * 1.4426950408889634f) : 1.0f;
    const int nn0 = n0 & 127;
    const int tx = threadIdx.x, ty = threadIdx.y;

    #pragma unroll
    for (int i = 0; i < 4; i++)
        t[ty * 4 + i][tx] = W[(size_t)(k0 + ty * 4 + i) * HSq + nn0 + tx] * sc;
    __syncthreads();
    #pragma unroll
    for (int i = 0; i < 4; i++) {
        int nr = ty * 4 + i;
        g_wt_h[(size_t)(n0 + nr) * Dq + k0 + tx] = __float2half_rn(t[tx][nr]);
    }
}

// ---------------------------------------------------------------------------
// Kernel 1: QKV projection, single-fp16 HMMA (1-term). BK=64 (16 chunks).
// Grid (128 M-tiles, 3 slabs), block 256 (8 warps, 4x2). BM=128 BN=128.
// ---------------------------------------------------------------------------
#define PS      144           // smem row pitch bytes (64 fp16 data + 8 pad)
#define P_ARR   (128 * PS)    // 18432
#define P_XH    0
#define P_WH    (1 * P_ARR)
#define P_BUF   (2 * P_ARR)   // 36864
#define PROJ_SMEM (2 * P_BUF) // 73728

__global__ __launch_bounds__(256, 2) void proj_mma_kernel()
{
    extern __shared__ __align__(16) char smc[];
    const uint32_t sb = smem_u32(smc);
    const int tid = threadIdx.x;
    const int w   = tid >> 5;
    const int L   = tid & 31;
    const int m0  = blockIdx.x * 128;
    const int nt  = blockIdx.y;                   // 0:q 1:k 2:v

    const __half* wh = g_wt_h + (size_t)nt * HSq * Dq;
    const __half* xh = g_x_h + (size_t)m0 * Dq;

    const int mrow  = (w & 3) * 32;
    const int nbase = (w >> 2) * 64;

    float c[2][8][4];
    #pragma unroll
    for (int mt = 0; mt < 2; mt++)
        #pragma unroll
        for (int j = 0; j < 8; j++)
            #pragma unroll
            for (int r = 0; r < 4; r++) c[mt][j][r] = 0.f;

    auto prefetch = [&](int ch, uint32_t bb) {
        const int kb = ch * 64;
        #pragma unroll
        for (int i = 0; i < 4; i++) {
            int idx = tid + i * 256;
            int r = idx >> 3, q = idx & 7;        // 8 x 16B = 128 bytes/row
            uint32_t d = bb + r * PS + q * 16;
            cp16(d + P_XH, xh + (size_t)r * Dq + kb + q * 8);
            cp16(d + P_WH, wh + (size_t)r * Dq + kb + q * 8);
        }
    };

    prefetch(0, sb);
    CP_COMMIT();

    for (int ch = 0; ch < Dq / 64; ch++) {
        if (ch + 1 < Dq / 64) prefetch(ch + 1, sb + ((ch + 1) & 1) * P_BUF);
        CP_COMMIT();
        CP_WAIT1();
        __syncthreads();

        const uint32_t base = sb + (ch & 1) * P_BUF;

        // A fragments: 2 mt x 4 k-steps, each ldsm.x4 = one 16x16 A fragment
        uint32_t ah[2][4][4];
        #pragma unroll
        for (int mt = 0; mt < 2; mt++) {
            uint32_t arow = base + P_XH
                + (uint32_t)(mrow + mt * 16 + (L & 7) + ((L >> 3) & 1) * 8) * PS
                + (L >> 4) * 16;
            #pragma unroll
            for (int ks = 0; ks < 4; ks++)
                ldsm_x4(ah[mt][ks], arow + ks * 32);
        }

        #pragma unroll
        for (int j = 0; j < 8; j++) {
            uint32_t brow = base + P_WH
                + (uint32_t)(nbase + 8 * j + (L & 7)) * PS + ((L >> 3) & 3) * 16;
            uint32_t bh[4], bh2[4];
            ldsm_x4(bh, brow);          // k 0-31
            ldsm_x4(bh2, brow + 64);    // k 32-63
            #pragma unroll
            for (int mt = 0; mt < 2; mt++) {
                mma_f16(c[mt][j], ah[mt][0], bh);
                mma_f16(c[mt][j], ah[mt][1], bh + 2);
                mma_f16(c[mt][j], ah[mt][2], bh2);
                mma_f16(c[mt][j], ah[mt][3], bh2 + 2);
            }
        }
        __syncthreads();
    }

    // Epilogue: q -> exact fp16 hi/lo; k, v -> single fp16
    #pragma unroll
    for (int mt = 0; mt < 2; mt++) {
        int r0 = m0 + mrow + mt * 16 + (L >> 2);
        #pragma unroll
        for (int j = 0; j < 8; j++) {
            int cc = nbase + 8 * j + (L & 3) * 2;
            if (nt != 0) {
                __half* o1 = (nt == 1) ? g_k : g_v;
                *(uint32_t*)&o1[(size_t)r0 * HSq + cc] = packh2(c[mt][j][0], c[mt][j][1]);
                *(uint32_t*)&o1[(size_t)(r0 + 8) * HSq + cc] = packh2(c[mt][j][2], c[mt][j][3]);
            } else {
                uint32_t h, l;
                split2h(c[mt][j][0], c[mt][j][1], h, l);
                *(uint32_t*)&g_q_hi[(size_t)r0 * HSq + cc] = h;
                *(uint32_t*)&g_q_lo[(size_t)r0 * HSq + cc] = l;
                split2h(c[mt][j][2], c[mt][j][3], h, l);
                *(uint32_t*)&g_q_hi[(size_t)(r0 + 8) * HSq + cc] = h;
                *(uint32_t*)&g_q_lo[(size_t)(r0 + 8) * HSq + cc] = l;
            }
        }
    }
}

// ---------------------------------------------------------------------------
// Kernel 2: split-KV causal flash attention, fp16 asymmetric.
// S = Qhi*K + Qlo*K (K single fp16, 2-term); O = P*V (both single fp16, 1-term).
// K double-buffered, V single-buffered. smem 52224, 2 CTAs/SM.
// Grid (8 batch, 48 chunks heavy-first). Block 128 (4 warps).
// ---------------------------------------------------------------------------
#define KV_ROWB 272                        // 128 fp16 data + 8 pad
#define KTILE   (64 * KV_ROWB)             // 17408
#define A_K0    0
#define A_K1    (1 * KTILE)
#define A_V     (2 * KTILE)
#define ATTN_SMEM (3 * KTILE)              // 52224

__global__ __launch_bounds__(128, 2) void attn_mma_kernel(float* __restrict__ out)
{
    extern __shared__ __align__(16) char smc[];
    const uint32_t sb = smem_u32(smc);
    const int tid = threadIdx.x;
    const int w   = tid >> 5;
    const int L   = tid & 31;
    const int b   = blockIdx.x;
    const int cid = blockIdx.y;
    const int qt  = c_qt[cid];
    const int kt0 = c_k0[cid];
    const int cnt = c_cnt[cid];
    const int q0  = qt * 64;

    const __half* qh_g = g_q_hi + (size_t)b * Tq * HSq;
    const __half* ql_g = g_q_lo + (size_t)b * Tq * HSq;
    const __half* k_g  = g_k + (size_t)b * Tq * HSq;
    const __half* v_g  = g_v + (size_t)b * Tq * HSq;

    const int lr = L >> 2;
    const int lc = (L & 3) * 2;

    auto prefetch_k = [&](int krow, int buf) {
        uint32_t kb = sb + (buf ? A_K1 : A_K0);
        #pragma unroll
        for (int i = 0; i < 8; i++) {
            int idx = tid + i * 128;
            int r = idx >> 4, q = idx & 15;
            cp16(kb + r * KV_ROWB + q * 16, k_g + (size_t)(krow + r) * HSq + q * 8);
        }
    };
    auto prefetch_v = [&](int krow) {
        #pragma unroll
        for (int i = 0; i < 8; i++) {
            int idx = tid + i * 128;
            int r = idx >> 4, q = idx & 15;
            cp16(sb + A_V + r * KV_ROWB + q * 16, v_g + (size_t)(krow + r) * HSq + q * 8);
        }
    };

    // Q fragments (pre-scaled by 128^-0.5*log2e, exact fp16 split)
    uint32_t qh[8][4], ql[8][4];
    #pragma unroll
    for (int s = 0; s < 8; s++)
        #pragma unroll
        for (int i = 0; i < 4; i++) {
            int rr = q0 + 16 * w + lr + 8 * (i & 1);
            int cc = 16 * s + lc + 8 * (i >> 1);
            qh[s][i] = *(const uint32_t*)&qh_g[(size_t)rr * HSq + cc];
            ql[s][i] = *(const uint32_t*)&ql_g[(size_t)rr * HSq + cc];
        }

    float o[16][4];
    #pragma unroll
    for (int j = 0; j < 16; j++)
        #pragma unroll
        for (int r = 0; r < 4; r++) o[j][r] = 0.f;
    float m0v = -1e30f, m1v = -1e30f, l0v = 0.f, l1v = 0.f;

    prefetch_k(kt0 * 64, 0); CP_COMMIT();
    prefetch_v(kt0 * 64);    CP_COMMIT();

    for (int t = 0; t < cnt; t++) {
        const int tile = kt0 + t;
        CP_WAIT1();           // K(t) complete
        __syncthreads();
        if (t + 1 < cnt) { prefetch_k((tile + 1) * 64, (t + 1) & 1); CP_COMMIT(); }

        const uint32_t kbuf = sb + ((t & 1) ? A_K1 : A_K0);

        // S = Q K^T : 2-term (Qhi, Qlo) x single-fp16 K
        float c[8][4];
        #pragma unroll
        for (int j = 0; j < 8; j++) {
            c[j][0] = c[j][1] = c[j][2] = c[j][3] = 0.f;
            uint32_t rowaddr = kbuf + (8 * j + (L & 7)) * KV_ROWB + ((L >> 3) & 3) * 16;
            #pragma unroll
            for (int sp = 0; sp < 4; sp++) {
                uint32_t bh[4];
                ldsm_x4(bh, rowaddr + 64 * sp);
                mma_f16(c[j], qh[2 * sp],     bh);
                mma_f16(c[j], ql[2 * sp],     bh);
                mma_f16(c[j], qh[2 * sp + 1], bh + 2);
                mma_f16(c[j], ql[2 * sp + 1], bh + 2);
            }
        }

        // Causal mask on diagonal tile
        if (tile == qt) {
            int r0 = 16 * w + lr, r1 = r0 + 8;
            #pragma unroll
            for (int j = 0; j < 8; j++) {
                int n0 = 8 * j + lc;
                if (n0 > r0)     c[j][0] = -1e30f;
                if (n0 + 1 > r0) c[j][1] = -1e30f;
                if (n0 > r1)     c[j][2] = -1e30f;
                if (n0 + 1 > r1) c[j][3] = -1e30f;
            }
        }

        // Online softmax (base-2); P packed to single fp16
        float mx0 = -1e30f, mx1 = -1e30f;
        #pragma unroll
        for (int j = 0; j < 8; j++) {
            mx0 = fmaxf(mx0, fmaxf(c[j][0], c[j][1]));
            mx1 = fmaxf(mx1, fmaxf(c[j][2], c[j][3]));
        }
        #pragma unroll
        for (int off = 1; off <= 2; off <<= 1) {
            mx0 = fmaxf(mx0, __shfl_xor_sync(0xffffffffu, mx0, off));
            mx1 = fmaxf(mx1, __shfl_xor_sync(0xffffffffu, mx1, off));
        }
        float mn0 = fmaxf(m0v, mx0), mn1 = fmaxf(m1v, mx1);
        float a0 = exp2f(m0v - mn0), a1 = exp2f(m1v - mn1);
        float rs0 = 0.f, rs1 = 0.f;
        uint32_t ph[8][2];
        #pragma unroll
        for (int j = 0; j < 8; j++) {
            float p0 = exp2f(c[j][0] - mn0);
            float p1 = exp2f(c[j][1] - mn0);
            float p2 = exp2f(c[j][2] - mn1);
            float p3 = exp2f(c[j][3] - mn1);
            rs0 += p0 + p1; rs1 += p2 + p3;
            ph[j][0] = packh2(p0, p1);
            ph[j][1] = packh2(p2, p3);
        }
        #pragma unroll
        for (int off = 1; off <= 2; off <<= 1) {
            rs0 += __shfl_xor_sync(0xffffffffu, rs0, off);
            rs1 += __shfl_xor_sync(0xffffffffu, rs1, off);
        }
        l0v = l0v * a0 + rs0;  m0v = mn0;
        l1v = l1v * a1 + rs1;  m1v = mn1;
        #pragma unroll
        for (int j = 0; j < 16; j++) {
            o[j][0] *= a0; o[j][1] *= a0;
            o[j][2] *= a1; o[j][3] *= a1;
        }

        // Wait for V(t)
        if (t + 1 < cnt) { CP_WAIT1(); } else { CP_WAIT0(); }
        __syncthreads();

        // O += P V : single-fp16 P x single-fp16 V (1-term)
        #pragma unroll
        for (int s = 0; s < 4; s++) {
            uint32_t ap[4] = { ph[2*s][0], ph[2*s][1], ph[2*s+1][0], ph[2*s+1][1] };
            uint32_t vaddr = sb + A_V + (16 * s + (L & 15)) * KV_ROWB + (L >> 4) * 16;
            #pragma unroll
            for (int jj = 0; jj < 16; jj += 2) {
                uint32_t bh[4];
                ldsm_x4_t(bh, vaddr + 16 * jj);
                mma_f16(o[jj],     ap, bh);
                mma_f16(o[jj + 1], ap, bh + 2);
            }
        }

        __syncthreads();
        if (t + 1 < cnt) { prefetch_v((tile + 1) * 64); CP_COMMIT(); }
    }

    const bool full = (kt0 == 0) && (cnt == qt + 1);   // covers entire causal range
    int r0 = 16 * w + lr;
    if (full) {
        float inv0 = __frcp_rn(l0v), inv1 = __frcp_rn(l1v);
        #pragma unroll
        for (int jj = 0; jj < 16; jj++) {
            int cc = 8 * jj + lc;
            *(float2*)&out[((size_t)b * Tq + q0 + r0) * HSq + cc] =
                make_float2(o[jj][0] * inv0, o[jj][1] * inv0);
            *(float2*)&out[((size_t)b * Tq + q0 + r0 + 8) * HSq + cc] =
                make_float2(o[jj][2] * inv1, o[jj][3] * inv1);
        }
    } else {
        const int part = (kt0 == 0) ? 0 : 1;
        const size_t pb = (((size_t)b * 32 + qt) * 2 + part) * (64 * 128);
        const size_t mb = (((size_t)b * 32 + qt) * 2 + part) * 64;
        #pragma unroll
        for (int jj = 0; jj < 16; jj++) {
            int cc = 8 * jj + lc;
            *(float2*)&g_po[pb + (size_t)r0 * 128 + cc] = make_float2(o[jj][0], o[jj][1]);
            *(float2*)&g_po[pb + (size_t)(r0 + 8) * 128 + cc] = make_float2(o[jj][2], o[jj][3]);
        }
        if ((L & 3) == 0) {
            g_pm[mb + r0] = m0v;  g_pl[mb + r0] = l0v;
            g_pm[mb + r0 + 8] = m1v;  g_pl[mb + r0 + 8] = l1v;
        }
    }
}

// ---------------------------------------------------------------------------
// Kernel 3: merge partials for qt >= 16 (two parts each). Grid (16, 8).
// ---------------------------------------------------------------------------
__global__ __launch_bounds__(256) void merge_kernel(float* __restrict__ out)
{
    const int qt = 16 + blockIdx.x;
    const int b  = blockIdx.y;
    const int tid = threadIdx.x;
    const size_t base0 = (((size_t)b * 32 + qt) * 2 + 0) * (64 * 128);
    const size_t base1 = base0 + 64 * 128;
    const size_t mb0 = (((size_t)b * 32 + qt) * 2 + 0) * 64;
    const size_t mb1 = mb0 + 64;

    #pragma unroll
    for (int i = 0; i < 8; i++) {
        int idx = tid + i * 256;        // float4 index, 2048 total
        int off = idx * 4;
        int row = off >> 7;
        int col = off & 127;
        float4 a = *(const float4*)&g_po[base0 + off];
        float4 bb = *(const float4*)&g_po[base1 + off];
        float mA = g_pm[mb0 + row], lA = g_pl[mb0 + row];
        float mB = g_pm[mb1 + row], lB = g_pl[mb1 + row];
        float m = fmaxf(mA, mB);
        float wA = exp2f(mA - m), wB = exp2f(mB - m);
        float inv = __frcp_rn(lA * wA + lB * wB);
        float4 res = make_float4((a.x * wA + bb.x * wB) * inv,
                                 (a.y * wA + bb.y * wB) * inv,
                                 (a.z * wA + bb.z * wB) * inv,
                                 (a.w * wA + bb.w * wB) * inv);
        *(float4*)&out[((size_t)b * Tq + qt * 64 + row) * HSq + col] = res;
    }
}

// ---------------------------------------------------------------------------
extern "C" void kernel_launch(void* const* d_in, const int* in_sizes, int n_in,
                              void* d_out, int out_size)
{
    const float* x  = (const float*)d_in[0];
    const float* Wq = (const float*)d_in[1];
    const float* Wk = (const float*)d_in[2];
    const float* Wv = (const float*)d_in[3];
    float* out = (float*)d_out;

    cudaFuncSetAttribute(proj_mma_kernel, cudaFuncAttributeMaxDynamicSharedMemorySize,
                         PROJ_SMEM);
    cudaFuncSetAttribute(attn_mma_kernel, cudaFuncAttributeMaxDynamicSharedMemorySize,
                         ATTN_SMEM);

    prep_x_kernel<<<BT * Dq / (256 * 8), 256>>>(x);

    dim3 wgrid(Dq / 32, NTOT / 32);
    prep_w_kernel<<<wgrid, dim3(32, 8)>>>(Wq, Wk, Wv);

    dim3 pgrid(BT / 128, 3);
    proj_mma_kernel<<<pgrid, 256, PROJ_SMEM>>>();

    dim3 agrid(Bq, 48);
    attn_mma_kernel<<<agrid, 128, ATTN_SMEM>>>(out);

    dim3 mgrid(16, Bq);
    merge_kernel<<<mgrid, 256>>>(out);
}

// round 15
// speedup vs baseline: 2.7866x; 1.1223x over previous
#include <cuda_runtime.h>
#include <cuda_bf16.h>
#include <cuda_fp16.h>
#include <math.h>
#include <cstdint>

#define Bq   8
#define Tq   2048
#define Dq   1024
#define HSq  128
#define BT   (Bq * Tq)        // 16384 rows
#define NTOT 384              // 3 * HS

// Scratch (device globals — no allocs allowed). All operands single fp16.
__device__ __align__(256) __half g_x_h[BT * Dq];             // x single fp16
__device__ __align__(256) __half g_wt_h[NTOT * Dq];          // W^T fp16 (Wq pre-scaled)
__device__ __align__(256) __half g_q[BT * HSq];              // q single fp16
__device__ __align__(256) __half g_k[BT * HSq];              // k single fp16
__device__ __align__(256) __half g_v[BT * HSq];              // v single fp16

// Split-KV partials: [b][qt][part][64][128] fp32 + per-row m,l (base-2 logits)
__device__ __align__(256) float g_po[Bq * 32 * 2 * 64 * 128];   // 16 MB
__device__ __align__(256) float g_pm[Bq * 32 * 2 * 64];
__device__ __align__(256) float g_pl[Bq * 32 * 2 * 64];

// Chunk LUT (48 chunks per batch), heavy-first (cnt descending).
__device__ const int c_qt[48]  = {15,16,17,18,19,20,21,22,23,24,25,26,27,28,29,30,31,31,
                                  14,30,13,29,12,28,11,27,10,26, 9,25, 8,24, 7,23,
                                   6,22, 5,21, 4,20, 3,19, 2,18, 1,17, 0,16};
__device__ const int c_k0[48]  = { 0, 0, 0, 0, 0, 0, 0, 0, 0, 0, 0, 0, 0, 0, 0, 0, 0,16,
                                   0,16, 0,16, 0,16, 0,16, 0,16, 0,16, 0,16, 0,16,
                                   0,16, 0,16, 0,16, 0,16, 0,16, 0,16, 0,16};
__device__ const int c_cnt[48] = {16,16,16,16,16,16,16,16,16,16,16,16,16,16,16,16,16,16,
                                  15,15,14,14,13,13,12,12,11,11,10,10, 9, 9, 8, 8,
                                   7, 7, 6, 6, 5, 5, 4, 4, 3, 3, 2, 2, 1, 1};

// ---------------------------------------------------------------------------
// Helpers
// ---------------------------------------------------------------------------
__device__ __forceinline__ void mma_f16(float* c, const uint32_t* a, const uint32_t* b) {
    asm volatile(
        "mma.sync.aligned.m16n8k16.row.col.f32.f16.f16.f32 "
        "{%0,%1,%2,%3}, {%4,%5,%6,%7}, {%8,%9}, {%0,%1,%2,%3};"
        : "+f"(c[0]), "+f"(c[1]), "+f"(c[2]), "+f"(c[3])
        : "r"(a[0]), "r"(a[1]), "r"(a[2]), "r"(a[3]), "r"(b[0]), "r"(b[1]));
}
__device__ __forceinline__ void ldsm_x4(uint32_t* r, uint32_t addr) {
    asm volatile("ldmatrix.sync.aligned.m8n8.x4.shared.b16 {%0,%1,%2,%3}, [%4];"
                 : "=r"(r[0]), "=r"(r[1]), "=r"(r[2]), "=r"(r[3]) : "r"(addr));
}
__device__ __forceinline__ void ldsm_x4_t(uint32_t* r, uint32_t addr) {
    asm volatile("ldmatrix.sync.aligned.m8n8.x4.trans.shared.b16 {%0,%1,%2,%3}, [%4];"
                 : "=r"(r[0]), "=r"(r[1]), "=r"(r[2]), "=r"(r[3]) : "r"(addr));
}
__device__ __forceinline__ uint32_t smem_u32(const void* p) {
    uint32_t a;
    asm("{ .reg .u64 t; cvta.to.shared.u64 t, %1; cvt.u32.u64 %0, t; }"
        : "=r"(a) : "l"(p));
    return a;
}
__device__ __forceinline__ void cp16(uint32_t dst, const void* src) {
    asm volatile("cp.async.cg.shared.global [%0], [%1], 16;" :: "r"(dst), "l"(src));
}
#define CP_COMMIT() asm volatile("cp.async.commit_group;" ::: "memory")
#define CP_WAIT0()  asm volatile("cp.async.wait_group 0;" ::: "memory")
#define CP_WAIT1()  asm volatile("cp.async.wait_group 1;" ::: "memory")

__device__ __forceinline__ uint32_t packh2(float v0, float v1) {
    __half2 h2 = __floats2half2_rn(v0, v1);
    return *(uint32_t*)&h2;
}

// ---------------------------------------------------------------------------
// Kernel 0a: convert x -> single fp16. 8 floats per thread.
// ---------------------------------------------------------------------------
__global__ __launch_bounds__(256) void prep_x_kernel(const float* __restrict__ x)
{
    size_t i = ((size_t)blockIdx.x * 256 + threadIdx.x) * 8;
    float4 a = *(const float4*)&x[i];
    float4 b = *(const float4*)&x[i + 4];
    *(uint4*)&g_x_h[i] = make_uint4(packh2(a.x, a.y), packh2(a.z, a.w),
                                    packh2(b.x, b.y), packh2(b.z, b.w));
}

// ---------------------------------------------------------------------------
// Kernel 0b: transpose + convert weights to fp16 (Wq scaled by 128^-0.5*log2e).
// ---------------------------------------------------------------------------
__global__ void prep_w_kernel(const float* __restrict__ Wq,
                              const float* __restrict__ Wk,
                              const float* __restrict__ Wv)
{
    __shared__ float t[32][33];
    const int k0 = blockIdx.x * 32;
    const int n0 = blockIdx.y * 32;
    const int slab = n0 >> 7;
    const float* W = (slab == 0) ? Wq : (slab == 1) ? Wk : Wv;
    const float sc = (slab == 0) ? (0.08838834764831845f * 1.4426950408889634f) : 1.0f;
    const int nn0 = n0 & 127;
    const int tx = threadIdx.x, ty = threadIdx.y;

    #pragma unroll
    for (int i = 0; i < 4; i++)
        t[ty * 4 + i][tx] = W[(size_t)(k0 + ty * 4 + i) * HSq + nn0 + tx] * sc;
    __syncthreads();
    #pragma unroll
    for (int i = 0; i < 4; i++) {
        int nr = ty * 4 + i;
        g_wt_h[(size_t)(n0 + nr) * Dq + k0 + tx] = __float2half_rn(t[tx][nr]);
    }
}

// ---------------------------------------------------------------------------
// Kernel 1: QKV projection, single-fp16 HMMA (1-term). BK=64 (16 chunks).
// Grid (128 M-tiles, 3 slabs), block 256 (8 warps, 4x2). BM=128 BN=128.
// ---------------------------------------------------------------------------
#define PS      144           // smem row pitch bytes (64 fp16 data + 8 pad)
#define P_ARR   (128 * PS)    // 18432
#define P_XH    0
#define P_WH    (1 * P_ARR)
#define P_BUF   (2 * P_ARR)   // 36864
#define PROJ_SMEM (2 * P_BUF) // 73728

__global__ __launch_bounds__(256, 2) void proj_mma_kernel()
{
    extern __shared__ __align__(16) char smc[];
    const uint32_t sb = smem_u32(smc);
    const int tid = threadIdx.x;
    const int w   = tid >> 5;
    const int L   = tid & 31;
    const int m0  = blockIdx.x * 128;
    const int nt  = blockIdx.y;                   // 0:q 1:k 2:v

    const __half* wh = g_wt_h + (size_t)nt * HSq * Dq;
    const __half* xh = g_x_h + (size_t)m0 * Dq;
    __half* outp = (nt == 0) ? g_q : (nt == 1) ? g_k : g_v;

    const int mrow  = (w & 3) * 32;
    const int nbase = (w >> 2) * 64;

    float c[2][8][4];
    #pragma unroll
    for (int mt = 0; mt < 2; mt++)
        #pragma unroll
        for (int j = 0; j < 8; j++)
            #pragma unroll
            for (int r = 0; r < 4; r++) c[mt][j][r] = 0.f;

    auto prefetch = [&](int ch, uint32_t bb) {
        const int kb = ch * 64;
        #pragma unroll
        for (int i = 0; i < 4; i++) {
            int idx = tid + i * 256;
            int r = idx >> 3, q = idx & 7;        // 8 x 16B = 128 bytes/row
            uint32_t d = bb + r * PS + q * 16;
            cp16(d + P_XH, xh + (size_t)r * Dq + kb + q * 8);
            cp16(d + P_WH, wh + (size_t)r * Dq + kb + q * 8);
        }
    };

    prefetch(0, sb);
    CP_COMMIT();

    for (int ch = 0; ch < Dq / 64; ch++) {
        if (ch + 1 < Dq / 64) prefetch(ch + 1, sb + ((ch + 1) & 1) * P_BUF);
        CP_COMMIT();
        CP_WAIT1();
        __syncthreads();

        const uint32_t base = sb + (ch & 1) * P_BUF;

        // A fragments: 2 mt x 4 k-steps, each ldsm.x4 = one 16x16 A fragment
        uint32_t ah[2][4][4];
        #pragma unroll
        for (int mt = 0; mt < 2; mt++) {
            uint32_t arow = base + P_XH
                + (uint32_t)(mrow + mt * 16 + (L & 7) + ((L >> 3) & 1) * 8) * PS
                + (L >> 4) * 16;
            #pragma unroll
            for (int ks = 0; ks < 4; ks++)
                ldsm_x4(ah[mt][ks], arow + ks * 32);
        }

        #pragma unroll
        for (int j = 0; j < 8; j++) {
            uint32_t brow = base + P_WH
                + (uint32_t)(nbase + 8 * j + (L & 7)) * PS + ((L >> 3) & 3) * 16;
            uint32_t bh[4], bh2[4];
            ldsm_x4(bh, brow);          // k 0-31
            ldsm_x4(bh2, brow + 64);    // k 32-63
            #pragma unroll
            for (int mt = 0; mt < 2; mt++) {
                mma_f16(c[mt][j], ah[mt][0], bh);
                mma_f16(c[mt][j], ah[mt][1], bh + 2);
                mma_f16(c[mt][j], ah[mt][2], bh2);
                mma_f16(c[mt][j], ah[mt][3], bh2 + 2);
            }
        }
        __syncthreads();
    }

    // Epilogue: single fp16 pack for q, k, v
    #pragma unroll
    for (int mt = 0; mt < 2; mt++) {
        int r0 = m0 + mrow + mt * 16 + (L >> 2);
        #pragma unroll
        for (int j = 0; j < 8; j++) {
            int cc = nbase + 8 * j + (L & 3) * 2;
            *(uint32_t*)&outp[(size_t)r0 * HSq + cc] = packh2(c[mt][j][0], c[mt][j][1]);
            *(uint32_t*)&outp[(size_t)(r0 + 8) * HSq + cc] = packh2(c[mt][j][2], c[mt][j][3]);
        }
    }
}

// ---------------------------------------------------------------------------
// Kernel 2: split-KV causal flash attention, single-fp16 everywhere (1-term).
// S = Q*K; O = P*V. K double-buffered, V single-buffered. smem 52224, 2 CTAs/SM.
// Grid (8 batch, 48 chunks heavy-first). Block 128 (4 warps).
// ---------------------------------------------------------------------------
#define KV_ROWB 272                        // 128 fp16 data + 8 pad
#define KTILE   (64 * KV_ROWB)             // 17408
#define A_K0    0
#define A_K1    (1 * KTILE)
#define A_V     (2 * KTILE)
#define ATTN_SMEM (3 * KTILE)              // 52224

__global__ __launch_bounds__(128, 2) void attn_mma_kernel(float* __restrict__ out)
{
    extern __shared__ __align__(16) char smc[];
    const uint32_t sb = smem_u32(smc);
    const int tid = threadIdx.x;
    const int w   = tid >> 5;
    const int L   = tid & 31;
    const int b   = blockIdx.x;
    const int cid = blockIdx.y;
    const int qt  = c_qt[cid];
    const int kt0 = c_k0[cid];
    const int cnt = c_cnt[cid];
    const int q0  = qt * 64;

    const __half* q_g = g_q + (size_t)b * Tq * HSq;
    const __half* k_g = g_k + (size_t)b * Tq * HSq;
    const __half* v_g = g_v + (size_t)b * Tq * HSq;

    const int lr = L >> 2;
    const int lc = (L & 3) * 2;

    auto prefetch_k = [&](int krow, int buf) {
        uint32_t kb = sb + (buf ? A_K1 : A_K0);
        #pragma unroll
        for (int i = 0; i < 8; i++) {
            int idx = tid + i * 128;
            int r = idx >> 4, q = idx & 15;
            cp16(kb + r * KV_ROWB + q * 16, k_g + (size_t)(krow + r) * HSq + q * 8);
        }
    };
    auto prefetch_v = [&](int krow) {
        #pragma unroll
        for (int i = 0; i < 8; i++) {
            int idx = tid + i * 128;
            int r = idx >> 4, q = idx & 15;
            cp16(sb + A_V + r * KV_ROWB + q * 16, v_g + (size_t)(krow + r) * HSq + q * 8);
        }
    };

    // Q fragments (pre-scaled by 128^-0.5*log2e), single fp16
    uint32_t qh[8][4];
    #pragma unroll
    for (int s = 0; s < 8; s++)
        #pragma unroll
        for (int i = 0; i < 4; i++) {
            int rr = q0 + 16 * w + lr + 8 * (i & 1);
            int cc = 16 * s + lc + 8 * (i >> 1);
            qh[s][i] = *(const uint32_t*)&q_g[(size_t)rr * HSq + cc];
        }

    float o[16][4];
    #pragma unroll
    for (int j = 0; j < 16; j++)
        #pragma unroll
        for (int r = 0; r < 4; r++) o[j][r] = 0.f;
    float m0v = -1e30f, m1v = -1e30f, l0v = 0.f, l1v = 0.f;

    prefetch_k(kt0 * 64, 0); CP_COMMIT();
    prefetch_v(kt0 * 64);    CP_COMMIT();

    for (int t = 0; t < cnt; t++) {
        const int tile = kt0 + t;
        CP_WAIT1();           // K(t) complete
        __syncthreads();
        if (t + 1 < cnt) { prefetch_k((tile + 1) * 64, (t + 1) & 1); CP_COMMIT(); }

        const uint32_t kbuf = sb + ((t & 1) ? A_K1 : A_K0);

        // S = Q K^T : single-fp16 1-term
        float c[8][4];
        #pragma unroll
        for (int j = 0; j < 8; j++) {
            c[j][0] = c[j][1] = c[j][2] = c[j][3] = 0.f;
            uint32_t rowaddr = kbuf + (8 * j + (L & 7)) * KV_ROWB + ((L >> 3) & 3) * 16;
            #pragma unroll
            for (int sp = 0; sp < 4; sp++) {
                uint32_t bh[4];
                ldsm_x4(bh, rowaddr + 64 * sp);
                mma_f16(c[j], qh[2 * sp],     bh);
                mma_f16(c[j], qh[2 * sp + 1], bh + 2);
            }
        }

        // Causal mask on diagonal tile
        if (tile == qt) {
            int r0 = 16 * w + lr, r1 = r0 + 8;
            #pragma unroll
            for (int j = 0; j < 8; j++) {
                int n0 = 8 * j + lc;
                if (n0 > r0)     c[j][0] = -1e30f;
                if (n0 + 1 > r0) c[j][1] = -1e30f;
                if (n0 > r1)     c[j][2] = -1e30f;
                if (n0 + 1 > r1) c[j][3] = -1e30f;
            }
        }

        // Online softmax (base-2); P packed to single fp16
        float mx0 = -1e30f, mx1 = -1e30f;
        #pragma unroll
        for (int j = 0; j < 8; j++) {
            mx0 = fmaxf(mx0, fmaxf(c[j][0], c[j][1]));
            mx1 = fmaxf(mx1, fmaxf(c[j][2], c[j][3]));
        }
        #pragma unroll
        for (int off = 1; off <= 2; off <<= 1) {
            mx0 = fmaxf(mx0, __shfl_xor_sync(0xffffffffu, mx0, off));
            mx1 = fmaxf(mx1, __shfl_xor_sync(0xffffffffu, mx1, off));
        }
        float mn0 = fmaxf(m0v, mx0), mn1 = fmaxf(m1v, mx1);
        float a0 = exp2f(m0v - mn0), a1 = exp2f(m1v - mn1);
        float rs0 = 0.f, rs1 = 0.f;
        uint32_t ph[8][2];
        #pragma unroll
        for (int j = 0; j < 8; j++) {
            float p0 = exp2f(c[j][0] - mn0);
            float p1 = exp2f(c[j][1] - mn0);
            float p2 = exp2f(c[j][2] - mn1);
            float p3 = exp2f(c[j][3] - mn1);
            rs0 += p0 + p1; rs1 += p2 + p3;
            ph[j][0] = packh2(p0, p1);
            ph[j][1] = packh2(p2, p3);
        }
        #pragma unroll
        for (int off = 1; off <= 2; off <<= 1) {
            rs0 += __shfl_xor_sync(0xffffffffu, rs0, off);
            rs1 += __shfl_xor_sync(0xffffffffu, rs1, off);
        }
        l0v = l0v * a0 + rs0;  m0v = mn0;
        l1v = l1v * a1 + rs1;  m1v = mn1;
        #pragma unroll
        for (int j = 0; j < 16; j++) {
            o[j][0] *= a0; o[j][1] *= a0;
            o[j][2] *= a1; o[j][3] *= a1;
        }

        // Wait for V(t)
        if (t + 1 < cnt) { CP_WAIT1(); } else { CP_WAIT0(); }
        __syncthreads();

        // O += P V : single-fp16 (1-term)
        #pragma unroll
        for (int s = 0; s < 4; s++) {
            uint32_t ap[4] = { ph[2*s][0], ph[2*s][1], ph[2*s+1][0], ph[2*s+1][1] };
            uint32_t vaddr = sb + A_V + (16 * s + (L & 15)) * KV_ROWB + (L >> 4) * 16;
            #pragma unroll
            for (int jj = 0; jj < 16; jj += 2) {
                uint32_t bh[4];
                ldsm_x4_t(bh, vaddr + 16 * jj);
                mma_f16(o[jj],     ap, bh);
                mma_f16(o[jj + 1], ap, bh + 2);
            }
        }

        __syncthreads();
        if (t + 1 < cnt) { prefetch_v((tile + 1) * 64); CP_COMMIT(); }
    }

    const bool full = (kt0 == 0) && (cnt == qt + 1);   // covers entire causal range
    int r0 = 16 * w + lr;
    if (full) {
        float inv0 = __frcp_rn(l0v), inv1 = __frcp_rn(l1v);
        #pragma unroll
        for (int jj = 0; jj < 16; jj++) {
            int cc = 8 * jj + lc;
            *(float2*)&out[((size_t)b * Tq + q0 + r0) * HSq + cc] =
                make_float2(o[jj][0] * inv0, o[jj][1] * inv0);
            *(float2*)&out[((size_t)b * Tq + q0 + r0 + 8) * HSq + cc] =
                make_float2(o[jj][2] * inv1, o[jj][3] * inv1);
        }
    } else {
        const int part = (kt0 == 0) ? 0 : 1;
        const size_t pb = (((size_t)b * 32 + qt) * 2 + part) * (64 * 128);
        const size_t mb = (((size_t)b * 32 + qt) * 2 + part) * 64;
        #pragma unroll
        for (int jj = 0; jj < 16; jj++) {
            int cc = 8 * jj + lc;
            *(float2*)&g_po[pb + (size_t)r0 * 128 + cc] = make_float2(o[jj][0], o[jj][1]);
            *(float2*)&g_po[pb + (size_t)(r0 + 8) * 128 + cc] = make_float2(o[jj][2], o[jj][3]);
        }
        if ((L & 3) == 0) {
            g_pm[mb + r0] = m0v;  g_pl[mb + r0] = l0v;
            g_pm[mb + r0 + 8] = m1v;  g_pl[mb + r0 + 8] = l1v;
        }
    }
}

// ---------------------------------------------------------------------------
// Kernel 3: merge partials for qt >= 16 (two parts each). Grid (16, 8).
// ---------------------------------------------------------------------------
__global__ __launch_bounds__(256) void merge_kernel(float* __restrict__ out)
{
    const int qt = 16 + blockIdx.x;
    const int b  = blockIdx.y;
    const int tid = threadIdx.x;
    const size_t base0 = (((size_t)b * 32 + qt) * 2 + 0) * (64 * 128);
    const size_t base1 = base0 + 64 * 128;
    const size_t mb0 = (((size_t)b * 32 + qt) * 2 + 0) * 64;
    const size_t mb1 = mb0 + 64;

    #pragma unroll
    for (int i = 0; i < 8; i++) {
        int idx = tid + i * 256;        // float4 index, 2048 total
        int off = idx * 4;
        int row = off >> 7;
        int col = off & 127;
        float4 a = *(const float4*)&g_po[base0 + off];
        float4 bb = *(const float4*)&g_po[base1 + off];
        float mA = g_pm[mb0 + row], lA = g_pl[mb0 + row];
        float mB = g_pm[mb1 + row], lB = g_pl[mb1 + row];
        float m = fmaxf(mA, mB);
        float wA = exp2f(mA - m), wB = exp2f(mB - m);
        float inv = __frcp_rn(lA * wA + lB * wB);
        float4 res = make_float4((a.x * wA + bb.x * wB) * inv,
                                 (a.y * wA + bb.y * wB) * inv,
                                 (a.z * wA + bb.z * wB) * inv,
                                 (a.w * wA + bb.w * wB) * inv);
        *(float4*)&out[((size_t)b * Tq + qt * 64 + row) * HSq + col] = res;
    }
}

// ---------------------------------------------------------------------------
extern "C" void kernel_launch(void* const* d_in, const int* in_sizes, int n_in,
                              void* d_out, int out_size)
{
    const float* x  = (const float*)d_in[0];
    const float* Wq = (const float*)d_in[1];
    const float* Wk = (const float*)d_in[2];
    const float* Wv = (const float*)d_in[3];
    float* out = (float*)d_out;

    cudaFuncSetAttribute(proj_mma_kernel, cudaFuncAttributeMaxDynamicSharedMemorySize,
                         PROJ_SMEM);
    cudaFuncSetAttribute(attn_mma_kernel, cudaFuncAttributeMaxDynamicSharedMemorySize,
                         ATTN_SMEM);

    prep_x_kernel<<<BT * Dq / (256 * 8), 256>>>(x);

    dim3 wgrid(Dq / 32, NTOT / 32);
    prep_w_kernel<<<wgrid, dim3(32, 8)>>>(Wq, Wk, Wv);

    dim3 pgrid(BT / 128, 3);
    proj_mma_kernel<<<pgrid, 256, PROJ_SMEM>>>();

    dim3 agrid(Bq, 48);
    attn_mma_kernel<<<agrid, 128, ATTN_SMEM>>>(out);

    dim3 mgrid(16, Bq);
    merge_kernel<<<mgrid, 256>>>(out);
}